// round 7
// baseline (speedup 1.0000x reference)
#include <cuda_runtime.h>
#include <cuda_fp16.h>
#include <math.h>
#include <stdint.h>

// Problem dimensions (fixed by the reference)
#define BB    4
#define SS    2048
#define DM    1024
#define HH    16
#define DK    64
#define DFF   4096
#define MROWS (BB*SS)          // 8192
#define QKVS  3072             // fused QKV row stride
#define LN_EPS 1e-5f

// ---------------------------------------------------------------------------
// Scratch (device globals; no allocations allowed)
// ---------------------------------------------------------------------------
__device__ __half g_h   [MROWS*DM];     // ln1 / ln2 output (fp16)
__device__ __half g_qkv [MROWS*QKVS];   // fused Q|K|V (fp16)
__device__ __half g_o   [MROWS*DM];     // attention output (fp16)
__device__ float  g_x1  [MROWS*DM];     // residual after attention (fp32)
__device__ __half g_ff  [MROWS*DFF];    // FFN hidden (fp16)
__device__ __half g_wqkvt[QKVS*DM];     // fused transposed weights [3072,1024]
__device__ __half g_wot [DM*DM];
__device__ __half g_w1t [DFF*DM];       // [4096,1024]
__device__ __half g_w2t [DM*DFF];       // [1024,4096]
__device__ float  g_bqkv[QKVS];         // fused bias

// ---------------------------------------------------------------------------
// Helpers
// ---------------------------------------------------------------------------
__device__ __forceinline__ uint32_t smem_u32(const void* p) {
    uint32_t a;
    asm("{ .reg .u64 t; cvta.to.shared.u64 t, %1; cvt.u32.u64 %0, t; }"
        : "=r"(a) : "l"(p));
    return a;
}

__device__ __forceinline__ uint32_t pack_h2(float lo, float hi) {
    __half2 h = __floats2half2_rn(lo, hi);
    return *reinterpret_cast<uint32_t*>(&h);
}

__device__ __forceinline__ float ex2(float x) {        // 2^x, MUFU.EX2
    float y;
    asm("ex2.approx.f32 %0, %1;" : "=f"(y) : "f"(x));
    return y;
}

#define CP_ASYNC16(dst, src) \
    asm volatile("cp.async.cg.shared.global [%0], [%1], 16;" :: "r"(dst), "l"(src))
#define CP_COMMIT()  asm volatile("cp.async.commit_group;" ::: "memory")
#define CP_WAIT(n)   asm volatile("cp.async.wait_group %0;" :: "n"(n) : "memory")

// m16n8k16 fp16 mma, fp32 accumulate
#define MMA_F16(d, a, b0, b1) \
    asm volatile("mma.sync.aligned.m16n8k16.row.col.f32.f16.f16.f32 " \
        "{%0,%1,%2,%3}, {%4,%5,%6,%7}, {%8,%9}, {%0,%1,%2,%3};" \
        : "+f"(d[0]), "+f"(d[1]), "+f"(d[2]), "+f"(d[3]) \
        : "r"(a[0]), "r"(a[1]), "r"(a[2]), "r"(a[3]), "r"(b0), "r"(b1))

#define LDSM_X4(r0, r1, r2, r3, addr) \
    asm volatile("ldmatrix.sync.aligned.m8n8.x4.shared.b16 {%0,%1,%2,%3}, [%4];" \
        : "=r"(r0), "=r"(r1), "=r"(r2), "=r"(r3) : "r"(addr))

#define LDSM_X2(r0, r1, addr) \
    asm volatile("ldmatrix.sync.aligned.m8n8.x2.shared.b16 {%0,%1}, [%2];" \
        : "=r"(r0), "=r"(r1) : "r"(addr))

#define LDSM_X4_TRANS(r0, r1, r2, r3, addr) \
    asm volatile("ldmatrix.sync.aligned.m8n8.x4.trans.shared.b16 {%0,%1,%2,%3}, [%4];" \
        : "=r"(r0), "=r"(r1), "=r"(r2), "=r"(r3) : "r"(addr))

// ---------------------------------------------------------------------------
// LayerNorm -> fp16 output
// ---------------------------------------------------------------------------
__global__ __launch_bounds__(256) void ln_kernel(
    const float* __restrict__ X, const float* __restrict__ gamma,
    const float* __restrict__ beta, __half* __restrict__ out)
{
    const int row = blockIdx.x;
    const int t   = threadIdx.x;
    const float4 v = ((const float4*)(X + (size_t)row*DM))[t];

    float s  = v.x + v.y + v.z + v.w;
    float ss = v.x*v.x + v.y*v.y + v.z*v.z + v.w*v.w;

    #pragma unroll
    for (int o = 16; o > 0; o >>= 1) {
        s  += __shfl_xor_sync(0xffffffffu, s,  o);
        ss += __shfl_xor_sync(0xffffffffu, ss, o);
    }
    __shared__ float sh_s[8], sh_ss[8];
    const int w = t >> 5, lane = t & 31;
    if (lane == 0) { sh_s[w] = s; sh_ss[w] = ss; }
    __syncthreads();
    if (w == 0) {
        s  = (lane < 8) ? sh_s[lane]  : 0.f;
        ss = (lane < 8) ? sh_ss[lane] : 0.f;
        #pragma unroll
        for (int o = 4; o > 0; o >>= 1) {
            s  += __shfl_xor_sync(0xffffffffu, s,  o);
            ss += __shfl_xor_sync(0xffffffffu, ss, o);
        }
        if (lane == 0) { sh_s[0] = s; sh_ss[0] = ss; }
    }
    __syncthreads();
    s = sh_s[0]; ss = sh_ss[0];

    const float mu   = s * (1.0f / DM);
    const float var  = ss * (1.0f / DM) - mu*mu;
    const float rstd = rsqrtf(var + LN_EPS);

    const float4 g4 = ((const float4*)gamma)[t];
    const float4 b4 = ((const float4*)beta)[t];
    uint2 st;
    st.x = pack_h2((v.x - mu)*rstd*g4.x + b4.x, (v.y - mu)*rstd*g4.y + b4.y);
    st.y = pack_h2((v.z - mu)*rstd*g4.z + b4.z, (v.w - mu)*rstd*g4.w + b4.w);
    ((uint2*)(out + (size_t)row*DM))[t] = st;
}

// ---------------------------------------------------------------------------
// Weight transpose + fp16 rounding: W[K,N] (f32) -> Wt[N,K] (f16)
// ---------------------------------------------------------------------------
__global__ __launch_bounds__(256) void transpose_round(
    const float* __restrict__ W, __half* __restrict__ Wt, int K, int N)
{
    __shared__ float tile[32][33];
    const int tx = threadIdx.x, ty = threadIdx.y;
    const int n0 = blockIdx.x * 32, k0 = blockIdx.y * 32;
    #pragma unroll
    for (int i = ty; i < 32; i += 8)
        tile[i][tx] = W[(size_t)(k0 + i)*N + n0 + tx];
    __syncthreads();
    #pragma unroll
    for (int i = ty; i < 32; i += 8)
        Wt[(size_t)(n0 + i)*K + k0 + tx] = __float2half_rn(tile[tx][i]);
}

// Four DMxDM transposes in one launch (Wq/Wk/Wv into fused buffer, Wo separate)
__global__ __launch_bounds__(256) void transpose_round4(
    const float* __restrict__ W0, const float* __restrict__ W1,
    const float* __restrict__ W2, const float* __restrict__ W3,
    __half* __restrict__ Tqkv, __half* __restrict__ To)
{
    const float* W; __half* T;
    switch (blockIdx.z) {
        case 0: W = W0; T = Tqkv;             break;
        case 1: W = W1; T = Tqkv + DM*DM;     break;
        case 2: W = W2; T = Tqkv + 2*DM*DM;   break;
        default: W = W3; T = To;              break;
    }
    __shared__ float tile[32][33];
    const int tx = threadIdx.x, ty = threadIdx.y;
    const int n0 = blockIdx.x * 32, k0 = blockIdx.y * 32;
    #pragma unroll
    for (int i = ty; i < 32; i += 8)
        tile[i][tx] = W[(size_t)(k0 + i)*DM + n0 + tx];
    __syncthreads();
    #pragma unroll
    for (int i = ty; i < 32; i += 8)
        T[(size_t)(n0 + i)*DM + k0 + tx] = __float2half_rn(tile[tx][i]);
}

// Fused QKV bias concat
__global__ __launch_bounds__(256) void bias_concat(
    const float* __restrict__ bq, const float* __restrict__ bk,
    const float* __restrict__ bv, float* __restrict__ out)
{
    const int i = blockIdx.x*256 + threadIdx.x;
    if (i < DM)            out[i] = bq[i];
    else if (i < 2*DM)     out[i] = bk[i - DM];
    else                   out[i] = bv[i - 2*DM];
}

// ---------------------------------------------------------------------------
// fp16 mma.sync GEMM: C[M,N] = A[M,K] @ Bt[N,K]^T + bias (+relu)(+res)
// CTA tile 128x256, BK=64, 3-stage cp.async, 256 threads (8 warps, 2x4).
// Warp tile 64x64 -> fragment bytes/FLOP cut 1.44x vs 64x32.
// ---------------------------------------------------------------------------
#define GST    3
#define LDH    72
#define A_H    (128*LDH)                  // 9216 halves
#define B_H    (256*LDH)                  // 18432 halves
#define STG_B  ((A_H + B_H)*2)            // 55296 B
#define GEMM_SMEM (GST*STG_B)             // 165888 B

template<bool RELU, bool RES, bool HALF_OUT>
__global__ __launch_bounds__(256, 1) void mma_gemm(
    const __half* __restrict__ A, const __half* __restrict__ Bt,
    const float* __restrict__ bias, const float* __restrict__ res,
    void* __restrict__ Cv, int M, int N, int K)
{
    extern __shared__ char smc[];
    const uint32_t sm_b = smem_u32(smc);

    const int tid  = threadIdx.x;
    const int lane = tid & 31, wid = tid >> 5;
    const int wm = wid >> 2, wn = wid & 3;        // 2 x 4 warp grid
    const int gid = lane >> 2, tg = lane & 3;
    const int bx = blockIdx.x, by = blockIdx.y;

    const __half* Ab = A  + (size_t)by * 128 * K;
    const __half* Bb = Bt + (size_t)bx * 256 * K;
    const int nchunks = K >> 6;                   // K/64

    // ldmatrix per-lane offsets (bytes) within a stage
    const int la7  = lane & 7;
    const int mrow = la7 + ((lane >> 3) & 1) * 8;
    const int mcol = (lane >> 4) * 8;
    uint32_t offA[4], offB[4];
    #pragma unroll
    for (int mt = 0; mt < 4; mt++)
        offA[mt] = (uint32_t)(((wm*64 + mt*16 + mrow)*LDH + mcol) * 2);
    #pragma unroll
    for (int nt2 = 0; nt2 < 4; nt2++)
        offB[nt2] = (uint32_t)((A_H + (wn*64 + nt2*16 + mrow)*LDH + mcol) * 2);

    // Stage loader: A 128x64, B 256x64 (16B chunks)
    auto load_stage = [&](int st, int kt) {
        const uint32_t a_dst = sm_b + (uint32_t)st*STG_B;
        const uint32_t b_dst = a_dst + A_H*2;
        const __half* as = Ab + (size_t)kt*64;
        const __half* bs = Bb + (size_t)kt*64;
        #pragma unroll
        for (int it = 0; it < 4; it++) {
            const int idx = it*256 + tid;
            const int r = idx >> 3, c8 = idx & 7;
            CP_ASYNC16(a_dst + (uint32_t)(r*144 + c8*16), as + (size_t)r*K + c8*8);
        }
        #pragma unroll
        for (int it = 0; it < 8; it++) {
            const int idx = it*256 + tid;
            const int r = idx >> 3, c8 = idx & 7;
            CP_ASYNC16(b_dst + (uint32_t)(r*144 + c8*16), bs + (size_t)r*K + c8*8);
        }
        CP_COMMIT();
    };

    float acc[4][8][4];
    #pragma unroll
    for (int i = 0; i < 4; i++)
        #pragma unroll
        for (int j = 0; j < 8; j++)
            #pragma unroll
            for (int k = 0; k < 4; k++) acc[i][j][k] = 0.f;

    load_stage(0, 0);
    if (nchunks > 1) load_stage(1, 1);

    for (int i = 0; i < nchunks; i++) {
        const int st = i % GST;
        if (i + 1 < nchunks) { CP_WAIT(1); } else { CP_WAIT(0); }
        __syncthreads();

        if (i + (GST-1) < nchunks)
            load_stage((i + GST - 1) % GST, i + GST - 1);

        const uint32_t base = sm_b + (uint32_t)st*STG_B;

        #pragma unroll
        for (int kk = 0; kk < 4; kk++) {
            uint32_t a[4][4], b[4][4];
            #pragma unroll
            for (int mt = 0; mt < 4; mt++)
                LDSM_X4(a[mt][0], a[mt][1], a[mt][2], a[mt][3],
                        base + offA[mt] + kk*32);
            #pragma unroll
            for (int nt2 = 0; nt2 < 4; nt2++)
                LDSM_X4(b[nt2][0], b[nt2][1], b[nt2][2], b[nt2][3],
                        base + offB[nt2] + kk*32);
            #pragma unroll
            for (int mt = 0; mt < 4; mt++) {
                #pragma unroll
                for (int nt2 = 0; nt2 < 4; nt2++) {
                    MMA_F16(acc[mt][2*nt2],   a[mt], b[nt2][0], b[nt2][2]);
                    MMA_F16(acc[mt][2*nt2+1], a[mt], b[nt2][1], b[nt2][3]);
                }
            }
        }
        __syncthreads();
    }

    // Epilogue
    #pragma unroll
    for (int mt = 0; mt < 4; mt++) {
        #pragma unroll
        for (int nt = 0; nt < 8; nt++) {
            const int r0 = by*128 + wm*64 + mt*16 + gid;
            const int c  = bx*256 + wn*64 + nt*8 + tg*2;
            const float2 b2 = *(const float2*)(bias + c);
            #pragma unroll
            for (int half_i = 0; half_i < 2; half_i++) {
                const int r = r0 + half_i*8;
                float ox = acc[mt][nt][half_i*2+0] + b2.x;
                float oy = acc[mt][nt][half_i*2+1] + b2.y;
                if (RELU) { ox = fmaxf(ox, 0.f); oy = fmaxf(oy, 0.f); }
                if (RES) {
                    const float2 r2 = *(const float2*)(res + (size_t)r*N + c);
                    ox += r2.x; oy += r2.y;
                }
                if (HALF_OUT) {
                    *(uint32_t*)((__half*)Cv + (size_t)r*N + c) = pack_h2(ox, oy);
                } else {
                    float2 o; o.x = ox; o.y = oy;
                    *(float2*)((float*)Cv + (size_t)r*N + c) = o;
                }
            }
        }
    }
}

// ---------------------------------------------------------------------------
// fp16 tensor-core causal flash attention, d_k=64, reading fused QKV buffer.
// CTA: 128 threads (4 warps), 64 q rows, 64-key KV tiles, double-buffered.
// ---------------------------------------------------------------------------
#define ALDH 72
#define ATILE_B (64*ALDH*2)               // 9216 B per 64x64 half tile
#define ATT_SMEM (4*ATILE_B)              // 36864 B
#define FA_C1 0.1803368801111204f          // log2(e)/8

__global__ __launch_bounds__(128) void fa_kernel(
    const __half* __restrict__ QKV, __half* __restrict__ O)
{
    extern __shared__ char fsc[];
    const int tid  = threadIdx.x;
    const int lane = tid & 31, w = tid >> 5;
    const int gid  = lane >> 2, tg = lane & 3;
    const int qt   = (int)gridDim.x - 1 - (int)blockIdx.x;   // big tiles first
    const int bh   = blockIdx.y;
    const int b    = bh >> 4, h = bh & 15;
    const int qbase = qt * 64;

    __half* Ks[2] = { (__half*)fsc,                 (__half*)(fsc + 2*ATILE_B) };
    __half* Vs[2] = { (__half*)(fsc + ATILE_B),     (__half*)(fsc + 3*ATILE_B) };

    auto load_tile = [&](__half* dst, const __half* src) {
        const uint32_t d0 = smem_u32(dst);
        #pragma unroll
        for (int i = 0; i < 4; i++) {
            const int idx = i*128 + tid;
            const int r = idx >> 3, c8 = idx & 7;
            CP_ASYNC16(d0 + (uint32_t)(r*144 + c8*16), src + (size_t)r*QKVS + c8*8);
        }
    };

    const __half* Kg = QKV + (size_t)(b*SS)*QKVS + DM + h*DK;
    const __half* Vg = QKV + (size_t)(b*SS)*QKVS + 2*DM + h*DK;
    auto load_kv = [&](int st, int kt) {
        load_tile(Ks[st], Kg + (size_t)(kt*64)*QKVS);
        load_tile(Vs[st], Vg + (size_t)(kt*64)*QKVS);
        CP_COMMIT();
    };

    // ldmatrix per-lane offsets
    const int la7 = lane & 7;
    const uint32_t offQ = (uint32_t)(((w*16 + la7 + ((lane>>3)&1)*8)*ALDH
                                     + (lane>>4)*8) * 2);
    uint32_t offK[8];
    #pragma unroll
    for (int nt = 0; nt < 8; nt++)
        offK[nt] = (uint32_t)(((nt*8 + la7)*ALDH + ((lane>>3)&1)*8) * 2);

    // --- Stage Q through smem, grab fp16 A fragments ---
    load_tile(Ks[0], QKV + (size_t)(b*SS + qbase)*QKVS + h*DK);
    CP_COMMIT();
    CP_WAIT(0);
    __syncthreads();

    uint32_t qf[4][4];
    {
        const uint32_t qsB = smem_u32(Ks[0]);
        #pragma unroll
        for (int kk = 0; kk < 4; kk++)
            LDSM_X4(qf[kk][0], qf[kk][1], qf[kk][2], qf[kk][3],
                    qsB + offQ + kk*32);
    }
    __syncthreads();

    load_kv(0, 0);
    if (qt >= 1) load_kv(1, 1);

    float oacc[8][4];
    #pragma unroll
    for (int d = 0; d < 8; d++) {
        oacc[d][0] = 0.f; oacc[d][1] = 0.f; oacc[d][2] = 0.f; oacc[d][3] = 0.f;
    }
    float m0r = -INFINITY, m1r = -INFINITY, l0 = 0.f, l1 = 0.f;

    for (int kt = 0; kt <= qt; kt++) {
        const int st = kt & 1;
        if (kt < qt) { CP_WAIT(1); } else { CP_WAIT(0); }
        __syncthreads();
        const uint32_t ks_b = smem_u32(Ks[st]);
        const uint32_t vs_b = smem_u32(Vs[st]);

        // ---- S = Q K^T (unscaled) ----
        float sacc[8][4];
        #pragma unroll
        for (int nt = 0; nt < 8; nt++) {
            sacc[nt][0] = 0.f; sacc[nt][1] = 0.f; sacc[nt][2] = 0.f; sacc[nt][3] = 0.f;
        }
        #pragma unroll
        for (int kk = 0; kk < 4; kk++) {
            #pragma unroll
            for (int nt = 0; nt < 8; nt++) {
                uint32_t b0, b1;
                LDSM_X2(b0, b1, ks_b + offK[nt] + kk*32);
                MMA_F16(sacc[nt], qf[kk], b0, b1);
            }
        }

        // ---- causal mask (diagonal tile only) ----
        if (kt == qt) {
            const int q0 = w*16 + gid;
            #pragma unroll
            for (int nt = 0; nt < 8; nt++) {
                const int s0 = nt*8 + 2*tg;
                if (s0     > q0)     sacc[nt][0] = -1e30f;
                if (s0 + 1 > q0)     sacc[nt][1] = -1e30f;
                if (s0     > q0 + 8) sacc[nt][2] = -1e30f;
                if (s0 + 1 > q0 + 8) sacc[nt][3] = -1e30f;
            }
        }

        // ---- online softmax in exp2 domain ----
        float t0 = -1e30f, t1 = -1e30f;
        #pragma unroll
        for (int nt = 0; nt < 8; nt++) {
            t0 = fmaxf(t0, fmaxf(sacc[nt][0], sacc[nt][1]));
            t1 = fmaxf(t1, fmaxf(sacc[nt][2], sacc[nt][3]));
        }
        t0 = fmaxf(t0, __shfl_xor_sync(0xffffffffu, t0, 1));
        t0 = fmaxf(t0, __shfl_xor_sync(0xffffffffu, t0, 2));
        t1 = fmaxf(t1, __shfl_xor_sync(0xffffffffu, t1, 1));
        t1 = fmaxf(t1, __shfl_xor_sync(0xffffffffu, t1, 2));

        const float mn0 = fmaxf(m0r, t0), mn1 = fmaxf(m1r, t1);
        const float cr0 = ex2((m0r - mn0) * FA_C1);
        const float cr1 = ex2((m1r - mn1) * FA_C1);
        m0r = mn0; m1r = mn1;
        l0 *= cr0; l1 *= cr1;
        #pragma unroll
        for (int d = 0; d < 8; d++) {
            oacc[d][0] *= cr0; oacc[d][1] *= cr0;
            oacc[d][2] *= cr1; oacc[d][3] *= cr1;
        }

        const float mc0 = mn0 * FA_C1, mc1 = mn1 * FA_C1;
        float s0 = 0.f, s1 = 0.f;
        #pragma unroll
        for (int nt = 0; nt < 8; nt++) {
            const float p0 = ex2(fmaf(sacc[nt][0], FA_C1, -mc0));
            const float p1 = ex2(fmaf(sacc[nt][1], FA_C1, -mc0));
            const float p2 = ex2(fmaf(sacc[nt][2], FA_C1, -mc1));
            const float p3 = ex2(fmaf(sacc[nt][3], FA_C1, -mc1));
            s0 += p0 + p1; s1 += p2 + p3;
            sacc[nt][0] = p0; sacc[nt][1] = p1; sacc[nt][2] = p2; sacc[nt][3] = p3;
        }
        s0 += __shfl_xor_sync(0xffffffffu, s0, 1);
        s0 += __shfl_xor_sync(0xffffffffu, s0, 2);
        s1 += __shfl_xor_sync(0xffffffffu, s1, 1);
        s1 += __shfl_xor_sync(0xffffffffu, s1, 2);
        l0 += s0; l1 += s1;

        // ---- O += P V ----
        const int lm = lane >> 3, lr = lane & 7;
        #pragma unroll
        for (int j = 0; j < 4; j++) {
            uint32_t a[4];
            a[0] = pack_h2(sacc[2*j  ][0], sacc[2*j  ][1]);
            a[1] = pack_h2(sacc[2*j  ][2], sacc[2*j  ][3]);
            a[2] = pack_h2(sacc[2*j+1][0], sacc[2*j+1][1]);
            a[3] = pack_h2(sacc[2*j+1][2], sacc[2*j+1][3]);
            #pragma unroll
            for (int dtp = 0; dtp < 4; dtp++) {
                const int s_a = j*16 + ((lm & 1) << 3) + lr;
                const int d_a = dtp*16 + ((lm >> 1) << 3);
                const uint32_t addr = vs_b + (uint32_t)(s_a*ALDH + d_a)*2;
                uint32_t b0, b1, b2, b3;
                LDSM_X4_TRANS(b0, b1, b2, b3, addr);
                MMA_F16(oacc[dtp*2],   a, b0, b1);
                MMA_F16(oacc[dtp*2+1], a, b2, b3);
            }
        }
        __syncthreads();

        if (kt + 2 <= qt) load_kv(st, kt + 2);
    }

    // ---- normalize + write (fp16; feeds Wo GEMM) ----
    const float inv0 = 1.0f / l0, inv1 = 1.0f / l1;
    const int r0 = b*SS + qbase + w*16 + gid;
    __half* o0 = O + (size_t)r0*DM + h*DK;
    __half* o1 = o0 + (size_t)8*DM;
    #pragma unroll
    for (int dt = 0; dt < 8; dt++) {
        const int c = dt*8 + 2*tg;
        *(uint32_t*)(o0 + c) = pack_h2(oacc[dt][0]*inv0, oacc[dt][1]*inv0);
        *(uint32_t*)(o1 + c) = pack_h2(oacc[dt][2]*inv1, oacc[dt][3]*inv1);
    }
}

// ---------------------------------------------------------------------------
// Launch
// ---------------------------------------------------------------------------
extern "C" void kernel_launch(void* const* d_in, const int* in_sizes, int n_in,
                              void* d_out, int out_size)
{
    const float* x   = (const float*)d_in[0];
    const float* Wq  = (const float*)d_in[1];
    const float* bq  = (const float*)d_in[2];
    const float* Wk  = (const float*)d_in[3];
    const float* bk  = (const float*)d_in[4];
    const float* Wv  = (const float*)d_in[5];
    const float* bv  = (const float*)d_in[6];
    const float* Wo  = (const float*)d_in[7];
    const float* bo  = (const float*)d_in[8];
    const float* W1  = (const float*)d_in[9];
    const float* b1  = (const float*)d_in[10];
    const float* W2  = (const float*)d_in[11];
    const float* b2  = (const float*)d_in[12];
    const float* g1  = (const float*)d_in[13];
    const float* be1 = (const float*)d_in[14];
    const float* g2  = (const float*)d_in[15];
    const float* be2 = (const float*)d_in[16];
    float* out = (float*)d_out;

    __half *p_h, *p_qkv, *p_o, *p_ff;
    __half *p_wqkvt, *p_wot, *p_w1t, *p_w2t;
    float  *p_x1, *p_bqkv;
    cudaGetSymbolAddress((void**)&p_h,     g_h);
    cudaGetSymbolAddress((void**)&p_qkv,   g_qkv);
    cudaGetSymbolAddress((void**)&p_o,     g_o);
    cudaGetSymbolAddress((void**)&p_x1,    g_x1);
    cudaGetSymbolAddress((void**)&p_ff,    g_ff);
    cudaGetSymbolAddress((void**)&p_wqkvt, g_wqkvt);
    cudaGetSymbolAddress((void**)&p_wot,   g_wot);
    cudaGetSymbolAddress((void**)&p_w1t,   g_w1t);
    cudaGetSymbolAddress((void**)&p_w2t,   g_w2t);
    cudaGetSymbolAddress((void**)&p_bqkv,  g_bqkv);

    static bool attr_set = false;
    if (!attr_set) {
        cudaFuncSetAttribute(mma_gemm<false,false,true>,
                             cudaFuncAttributeMaxDynamicSharedMemorySize, GEMM_SMEM);
        cudaFuncSetAttribute(mma_gemm<false,true,false>,
                             cudaFuncAttributeMaxDynamicSharedMemorySize, GEMM_SMEM);
        cudaFuncSetAttribute(mma_gemm<true,false,true>,
                             cudaFuncAttributeMaxDynamicSharedMemorySize, GEMM_SMEM);
        cudaFuncSetAttribute(fa_kernel,
                             cudaFuncAttributeMaxDynamicSharedMemorySize, ATT_SMEM);
        attr_set = true;
    }

    const dim3 tblk(32, 8);
    // Weight prep: Wq/Wk/Wv into fused buffer + Wo; FFN transposes; bias concat
    transpose_round4<<<dim3(DM/32, DM/32, 4), tblk>>>(
        Wq, Wk, Wv, Wo, p_wqkvt, p_wot);
    transpose_round<<<dim3(DFF/32, DM/32),  tblk>>>(W1, p_w1t, DM,  DFF);
    transpose_round<<<dim3(DM/32,  DFF/32), tblk>>>(W2, p_w2t, DFF, DM);
    bias_concat<<<QKVS/256, 256>>>(bq, bk, bv, p_bqkv);

    const dim3 gQKV(QKVS/256, MROWS/128);  // (12, 64)
    const dim3 gD  (DM/256,   MROWS/128);  // (4, 64)
    const dim3 gF  (DFF/256,  MROWS/128);  // (16, 64)

    // 1. ln1(x) -> h (fp16)
    ln_kernel<<<MROWS, 256>>>(x, g1, be1, p_h);
    // 2. fused QKV projection (fp16 tensor pipe, N=3072)
    mma_gemm<false,false,true><<<gQKV, 256, GEMM_SMEM>>>(p_h, p_wqkvt, p_bqkv, nullptr, p_qkv, MROWS, QKVS, DM);
    // 3. causal attention (fp16 flash attention over fused buffer)
    fa_kernel<<<dim3(SS/64, BB*HH), 128, ATT_SMEM>>>(p_qkv, p_o);
    // 4. output projection + residual(x) -> x1 (fp32)
    mma_gemm<false,true,false><<<gD, 256, GEMM_SMEM>>>(p_o, p_wot, bo, x, p_x1, MROWS, DM, DM);
    // 5. ln2(x1) -> h (fp16)
    ln_kernel<<<MROWS, 256>>>(p_x1, g2, be2, p_h);
    // 6. FFN up + ReLU (fp16 out)
    mma_gemm<true,false,true><<<gF, 256, GEMM_SMEM>>>(p_h, p_w1t, b1, nullptr, p_ff, MROWS, DFF, DM);
    // 7. FFN down + residual(x1) -> out (fp32)
    mma_gemm<false,true,false><<<gD, 256, GEMM_SMEM>>>(p_ff, p_w2t, b2, p_x1, out, MROWS, DM, DFF);
}

// round 8
// speedup vs baseline: 1.1162x; 1.1162x over previous
#include <cuda_runtime.h>
#include <cuda_fp16.h>
#include <math.h>
#include <stdint.h>

// Problem dimensions (fixed by the reference)
#define BB    4
#define SS    2048
#define DM    1024
#define HH    16
#define DK    64
#define DFF   4096
#define MROWS (BB*SS)          // 8192
#define QKVS  3072             // fused QKV row stride
#define LN_EPS 1e-5f

// ---------------------------------------------------------------------------
// Scratch (device globals; no allocations allowed)
// ---------------------------------------------------------------------------
__device__ __half g_h   [MROWS*DM];     // ln1 / ln2 output (fp16)
__device__ __half g_qkv [MROWS*QKVS];   // fused Q|K|V (fp16)
__device__ __half g_o   [MROWS*DM];     // attention output (fp16)
__device__ float  g_x1  [MROWS*DM];     // residual after attention (fp32)
__device__ __half g_ff  [MROWS*DFF];    // FFN hidden (fp16)
__device__ __half g_wqkvt[QKVS*DM];     // fused transposed weights [3072,1024]
__device__ __half g_wot [DM*DM];
__device__ __half g_w1t [DFF*DM];       // [4096,1024]
__device__ __half g_w2t [DM*DFF];       // [1024,4096]
__device__ float  g_bqkv[QKVS];         // fused bias

// ---------------------------------------------------------------------------
// Helpers
// ---------------------------------------------------------------------------
__device__ __forceinline__ uint32_t smem_u32(const void* p) {
    uint32_t a;
    asm("{ .reg .u64 t; cvta.to.shared.u64 t, %1; cvt.u32.u64 %0, t; }"
        : "=r"(a) : "l"(p));
    return a;
}

__device__ __forceinline__ uint32_t pack_h2(float lo, float hi) {
    __half2 h = __floats2half2_rn(lo, hi);
    return *reinterpret_cast<uint32_t*>(&h);
}

__device__ __forceinline__ float ex2(float x) {        // 2^x, MUFU.EX2
    float y;
    asm("ex2.approx.f32 %0, %1;" : "=f"(y) : "f"(x));
    return y;
}

#define CP_ASYNC16(dst, src) \
    asm volatile("cp.async.cg.shared.global [%0], [%1], 16;" :: "r"(dst), "l"(src))
#define CP_COMMIT()  asm volatile("cp.async.commit_group;" ::: "memory")
#define CP_WAIT(n)   asm volatile("cp.async.wait_group %0;" :: "n"(n) : "memory")

// m16n8k16 fp16 mma, fp32 accumulate
#define MMA_F16(d, a, b0, b1) \
    asm volatile("mma.sync.aligned.m16n8k16.row.col.f32.f16.f16.f32 " \
        "{%0,%1,%2,%3}, {%4,%5,%6,%7}, {%8,%9}, {%0,%1,%2,%3};" \
        : "+f"(d[0]), "+f"(d[1]), "+f"(d[2]), "+f"(d[3]) \
        : "r"(a[0]), "r"(a[1]), "r"(a[2]), "r"(a[3]), "r"(b0), "r"(b1))

#define LDSM_X4(r0, r1, r2, r3, addr) \
    asm volatile("ldmatrix.sync.aligned.m8n8.x4.shared.b16 {%0,%1,%2,%3}, [%4];" \
        : "=r"(r0), "=r"(r1), "=r"(r2), "=r"(r3) : "r"(addr))

#define LDSM_X2(r0, r1, addr) \
    asm volatile("ldmatrix.sync.aligned.m8n8.x2.shared.b16 {%0,%1}, [%2];" \
        : "=r"(r0), "=r"(r1) : "r"(addr))

#define LDSM_X4_TRANS(r0, r1, r2, r3, addr) \
    asm volatile("ldmatrix.sync.aligned.m8n8.x4.trans.shared.b16 {%0,%1,%2,%3}, [%4];" \
        : "=r"(r0), "=r"(r1), "=r"(r2), "=r"(r3) : "r"(addr))

// ---------------------------------------------------------------------------
// LayerNorm -> fp16 output
// ---------------------------------------------------------------------------
__global__ __launch_bounds__(256) void ln_kernel(
    const float* __restrict__ X, const float* __restrict__ gamma,
    const float* __restrict__ beta, __half* __restrict__ out)
{
    const int row = blockIdx.x;
    const int t   = threadIdx.x;
    const float4 v = ((const float4*)(X + (size_t)row*DM))[t];

    float s  = v.x + v.y + v.z + v.w;
    float ss = v.x*v.x + v.y*v.y + v.z*v.z + v.w*v.w;

    #pragma unroll
    for (int o = 16; o > 0; o >>= 1) {
        s  += __shfl_xor_sync(0xffffffffu, s,  o);
        ss += __shfl_xor_sync(0xffffffffu, ss, o);
    }
    __shared__ float sh_s[8], sh_ss[8];
    const int w = t >> 5, lane = t & 31;
    if (lane == 0) { sh_s[w] = s; sh_ss[w] = ss; }
    __syncthreads();
    if (w == 0) {
        s  = (lane < 8) ? sh_s[lane]  : 0.f;
        ss = (lane < 8) ? sh_ss[lane] : 0.f;
        #pragma unroll
        for (int o = 4; o > 0; o >>= 1) {
            s  += __shfl_xor_sync(0xffffffffu, s,  o);
            ss += __shfl_xor_sync(0xffffffffu, ss, o);
        }
        if (lane == 0) { sh_s[0] = s; sh_ss[0] = ss; }
    }
    __syncthreads();
    s = sh_s[0]; ss = sh_ss[0];

    const float mu   = s * (1.0f / DM);
    const float var  = ss * (1.0f / DM) - mu*mu;
    const float rstd = rsqrtf(var + LN_EPS);

    const float4 g4 = ((const float4*)gamma)[t];
    const float4 b4 = ((const float4*)beta)[t];
    uint2 st;
    st.x = pack_h2((v.x - mu)*rstd*g4.x + b4.x, (v.y - mu)*rstd*g4.y + b4.y);
    st.y = pack_h2((v.z - mu)*rstd*g4.z + b4.z, (v.w - mu)*rstd*g4.w + b4.w);
    ((uint2*)(out + (size_t)row*DM))[t] = st;
}

// ---------------------------------------------------------------------------
// Weight transpose + fp16 rounding: W[K,N] (f32) -> Wt[N,K] (f16)
// ---------------------------------------------------------------------------
__global__ __launch_bounds__(256) void transpose_round(
    const float* __restrict__ W, __half* __restrict__ Wt, int K, int N)
{
    __shared__ float tile[32][33];
    const int tx = threadIdx.x, ty = threadIdx.y;
    const int n0 = blockIdx.x * 32, k0 = blockIdx.y * 32;
    #pragma unroll
    for (int i = ty; i < 32; i += 8)
        tile[i][tx] = W[(size_t)(k0 + i)*N + n0 + tx];
    __syncthreads();
    #pragma unroll
    for (int i = ty; i < 32; i += 8)
        Wt[(size_t)(n0 + i)*K + k0 + tx] = __float2half_rn(tile[tx][i]);
}

// Four DMxDM transposes in one launch (Wq/Wk/Wv into fused buffer, Wo separate)
__global__ __launch_bounds__(256) void transpose_round4(
    const float* __restrict__ W0, const float* __restrict__ W1,
    const float* __restrict__ W2, const float* __restrict__ W3,
    __half* __restrict__ Tqkv, __half* __restrict__ To)
{
    const float* W; __half* T;
    switch (blockIdx.z) {
        case 0: W = W0; T = Tqkv;             break;
        case 1: W = W1; T = Tqkv + DM*DM;     break;
        case 2: W = W2; T = Tqkv + 2*DM*DM;   break;
        default: W = W3; T = To;              break;
    }
    __shared__ float tile[32][33];
    const int tx = threadIdx.x, ty = threadIdx.y;
    const int n0 = blockIdx.x * 32, k0 = blockIdx.y * 32;
    #pragma unroll
    for (int i = ty; i < 32; i += 8)
        tile[i][tx] = W[(size_t)(k0 + i)*DM + n0 + tx];
    __syncthreads();
    #pragma unroll
    for (int i = ty; i < 32; i += 8)
        T[(size_t)(n0 + i)*DM + k0 + tx] = __float2half_rn(tile[tx][i]);
}

// Fused QKV bias concat
__global__ __launch_bounds__(256) void bias_concat(
    const float* __restrict__ bq, const float* __restrict__ bk,
    const float* __restrict__ bv, float* __restrict__ out)
{
    const int i = blockIdx.x*256 + threadIdx.x;
    if (i < DM)            out[i] = bq[i];
    else if (i < 2*DM)     out[i] = bk[i - DM];
    else                   out[i] = bv[i - 2*DM];
}

// ---------------------------------------------------------------------------
// fp16 mma.sync GEMM (R6 geometry): C[M,N] = A[M,K] @ Bt[N,K]^T + bias
// 128x128 CTA tile, BK=64, 3-stage cp.async, 256 threads (8 warps, 2x4),
// warp tile 64x32, ldmatrix fragments, 2 CTAs/SM.
// ---------------------------------------------------------------------------
#define GST    3
#define LDH    72
#define TILE_H (128*LDH)                 // halves per tile (9216)
#define STAGE_BYTES (2*TILE_H*2)         // A + B = 36864 B
#define GEMM_SMEM (GST*STAGE_BYTES)      // 110592 B

template<bool RELU, bool RES, bool HALF_OUT>
__global__ __launch_bounds__(256, 2) void mma_gemm(
    const __half* __restrict__ A, const __half* __restrict__ Bt,
    const float* __restrict__ bias, const float* __restrict__ res,
    void* __restrict__ Cv, int M, int N, int K)
{
    extern __shared__ char smc[];
    const uint32_t sm_b = smem_u32(smc);

    const int tid  = threadIdx.x;
    const int lane = tid & 31, wid = tid >> 5;
    const int wm = wid >> 2, wn = wid & 3;        // 2 x 4 warp grid
    const int gid = lane >> 2, tg = lane & 3;
    const int bx = blockIdx.x, by = blockIdx.y;

    const __half* Ab = A  + (size_t)by * 128 * K;
    const __half* Bb = Bt + (size_t)bx * 128 * K;
    const int nchunks = K >> 6;                   // K/64

    // ldmatrix per-lane offsets (bytes) within a stage's A / B tile
    const int la7 = lane & 7;
    uint32_t offA[4], offB[4];
    {
        const int arow = la7 + ((lane >> 3) & 1) * 8;
        const int acol = (lane >> 4) * 8;
        #pragma unroll
        for (int mt = 0; mt < 4; mt++)
            offA[mt] = (uint32_t)(((wm*64 + mt*16 + arow)*LDH + acol) * 2);
        const int bcol = ((lane >> 3) & 1) * 8;
        #pragma unroll
        for (int nt = 0; nt < 4; nt++)
            offB[nt] = (uint32_t)(((wn*32 + nt*8 + la7)*LDH + bcol) * 2);
    }

    // Stage loader: 2 tiles x 128 rows x 64 halves (8x16B per row)
    auto load_stage = [&](int st, int kt) {
        const uint32_t a_dst = sm_b + (uint32_t)st*STAGE_BYTES;
        const uint32_t b_dst = a_dst + TILE_H*2;
        const __half* as = Ab + (size_t)kt*64;
        const __half* bs = Bb + (size_t)kt*64;
        #pragma unroll
        for (int it = 0; it < 4; it++) {
            const int idx = it*256 + tid;
            const int r = idx >> 3, c8 = idx & 7;
            const uint32_t off = (uint32_t)(r*144 + c8*16);
            CP_ASYNC16(a_dst + off, as + (size_t)r*K + c8*8);
            CP_ASYNC16(b_dst + off, bs + (size_t)r*K + c8*8);
        }
        CP_COMMIT();
    };

    float acc[4][4][4];
    #pragma unroll
    for (int i = 0; i < 4; i++)
        #pragma unroll
        for (int j = 0; j < 4; j++)
            #pragma unroll
            for (int k = 0; k < 4; k++) acc[i][j][k] = 0.f;

    load_stage(0, 0);
    if (nchunks > 1) load_stage(1, 1);

    for (int i = 0; i < nchunks; i++) {
        const int st = i % GST;
        if (i + 1 < nchunks) { CP_WAIT(1); } else { CP_WAIT(0); }
        __syncthreads();

        if (i + (GST-1) < nchunks)
            load_stage((i + GST - 1) % GST, i + GST - 1);

        const uint32_t aBase = sm_b + (uint32_t)st*STAGE_BYTES;
        const uint32_t bBase = aBase + TILE_H*2;

        #pragma unroll
        for (int kk = 0; kk < 4; kk++) {
            uint32_t a[4][4], b[4][2];
            #pragma unroll
            for (int mt = 0; mt < 4; mt++)
                LDSM_X4(a[mt][0], a[mt][1], a[mt][2], a[mt][3],
                        aBase + offA[mt] + kk*32);
            #pragma unroll
            for (int nt = 0; nt < 4; nt++)
                LDSM_X2(b[nt][0], b[nt][1], bBase + offB[nt] + kk*32);
            #pragma unroll
            for (int mt = 0; mt < 4; mt++)
                #pragma unroll
                for (int nt = 0; nt < 4; nt++)
                    MMA_F16(acc[mt][nt], a[mt], b[nt][0], b[nt][1]);
        }
        __syncthreads();
    }

    // Epilogue
    #pragma unroll
    for (int mt = 0; mt < 4; mt++) {
        #pragma unroll
        for (int nt = 0; nt < 4; nt++) {
            const int r0 = by*128 + wm*64 + mt*16 + gid;
            const int c  = bx*128 + wn*32 + nt*8 + tg*2;
            const float2 b2 = *(const float2*)(bias + c);
            #pragma unroll
            for (int half_i = 0; half_i < 2; half_i++) {
                const int r = r0 + half_i*8;
                float ox = acc[mt][nt][half_i*2+0] + b2.x;
                float oy = acc[mt][nt][half_i*2+1] + b2.y;
                if (RELU) { ox = fmaxf(ox, 0.f); oy = fmaxf(oy, 0.f); }
                if (RES) {
                    const float2 r2 = *(const float2*)(res + (size_t)r*N + c);
                    ox += r2.x; oy += r2.y;
                }
                if (HALF_OUT) {
                    *(uint32_t*)((__half*)Cv + (size_t)r*N + c) = pack_h2(ox, oy);
                } else {
                    float2 o; o.x = ox; o.y = oy;
                    *(float2*)((float*)Cv + (size_t)r*N + c) = o;
                }
            }
        }
    }
}

// ---------------------------------------------------------------------------
// fp16 tensor-core causal flash attention, d_k=64, fused QKV input.
// CTA: 256 threads (8 warps), 128 q rows (16/warp), 64-key KV tiles,
// double-buffered cp.async. Each K/V tile is shared by 8 warps -> half the
// smem fragment + cp.async traffic per FLOP vs the 64-row version.
// ---------------------------------------------------------------------------
#define ALDH 72
#define ATILE_B (64*ALDH*2)               // 9216 B per 64x64 half tile
#define ATT_SMEM (4*ATILE_B)              // 36864 B
#define FA_C1 0.1803368801111204f          // log2(e)/8

__global__ __launch_bounds__(256) void fa_kernel(
    const __half* __restrict__ QKV, __half* __restrict__ O)
{
    extern __shared__ char fsc[];
    const int tid  = threadIdx.x;
    const int lane = tid & 31, w = tid >> 5;      // 8 warps
    const int gid  = lane >> 2, tg = lane & 3;
    const int qt   = (int)gridDim.x - 1 - (int)blockIdx.x;   // big tiles first
    const int bh   = blockIdx.y;
    const int b    = bh >> 4, h = bh & 15;
    const int qbase = qt * 128;
    const int n_kt  = 2*qt + 2;                   // 64-key tiles to process

    __half* Ks[2] = { (__half*)fsc,                 (__half*)(fsc + 2*ATILE_B) };
    __half* Vs[2] = { (__half*)(fsc + ATILE_B),     (__half*)(fsc + 3*ATILE_B) };

    // 64-row tile loader (256 threads, 2 chunks each)
    auto load_tile = [&](__half* dst, const __half* src) {
        const uint32_t d0 = smem_u32(dst);
        #pragma unroll
        for (int i = 0; i < 2; i++) {
            const int idx = i*256 + tid;
            const int r = idx >> 3, c8 = idx & 7;
            CP_ASYNC16(d0 + (uint32_t)(r*144 + c8*16), src + (size_t)r*QKVS + c8*8);
        }
    };

    const __half* Kg = QKV + (size_t)(b*SS)*QKVS + DM + h*DK;
    const __half* Vg = QKV + (size_t)(b*SS)*QKVS + 2*DM + h*DK;
    auto load_kv = [&](int st, int kt) {
        load_tile(Ks[st], Kg + (size_t)(kt*64)*QKVS);
        load_tile(Vs[st], Vg + (size_t)(kt*64)*QKVS);
        CP_COMMIT();
    };

    // ldmatrix per-lane offsets
    const int la7 = lane & 7;
    const uint32_t offQ = (uint32_t)(((w*16 + la7 + ((lane>>3)&1)*8)*ALDH
                                     + (lane>>4)*8) * 2);
    uint32_t offK[8];
    #pragma unroll
    for (int nt = 0; nt < 8; nt++)
        offK[nt] = (uint32_t)(((nt*8 + la7)*ALDH + ((lane>>3)&1)*8) * 2);

    // --- Stage 128-row Q tile through smem (uses Ks[0]+Vs[0] region) ---
    {
        const uint32_t d0 = smem_u32(fsc);
        const __half* qsrc = QKV + (size_t)(b*SS + qbase)*QKVS + h*DK;
        #pragma unroll
        for (int i = 0; i < 4; i++) {
            const int idx = i*256 + tid;
            const int r = idx >> 3, c8 = idx & 7;
            CP_ASYNC16(d0 + (uint32_t)(r*144 + c8*16), qsrc + (size_t)r*QKVS + c8*8);
        }
        CP_COMMIT();
        CP_WAIT(0);
    }
    __syncthreads();

    uint32_t qf[4][4];
    {
        const uint32_t qsB = smem_u32(fsc);
        #pragma unroll
        for (int kk = 0; kk < 4; kk++)
            LDSM_X4(qf[kk][0], qf[kk][1], qf[kk][2], qf[kk][3],
                    qsB + offQ + kk*32);
    }
    __syncthreads();

    load_kv(0, 0);
    if (n_kt > 1) load_kv(1, 1);

    float oacc[8][4];
    #pragma unroll
    for (int d = 0; d < 8; d++) {
        oacc[d][0] = 0.f; oacc[d][1] = 0.f; oacc[d][2] = 0.f; oacc[d][3] = 0.f;
    }
    float m0r = -INFINITY, m1r = -INFINITY, l0 = 0.f, l1 = 0.f;

    for (int kt = 0; kt < n_kt; kt++) {
        const int st = kt & 1;
        if (kt + 1 < n_kt) { CP_WAIT(1); } else { CP_WAIT(0); }
        __syncthreads();
        const uint32_t ks_b = smem_u32(Ks[st]);
        const uint32_t vs_b = smem_u32(Vs[st]);

        // ---- S = Q K^T (unscaled) ----
        float sacc[8][4];
        #pragma unroll
        for (int nt = 0; nt < 8; nt++) {
            sacc[nt][0] = 0.f; sacc[nt][1] = 0.f; sacc[nt][2] = 0.f; sacc[nt][3] = 0.f;
        }
        #pragma unroll
        for (int kk = 0; kk < 4; kk++) {
            #pragma unroll
            for (int nt = 0; nt < 8; nt++) {
                uint32_t b0, b1;
                LDSM_X2(b0, b1, ks_b + offK[nt] + kk*32);
                MMA_F16(sacc[nt], qf[kk], b0, b1);
            }
        }

        // ---- causal mask (last two tiles only) ----
        if (kt >= n_kt - 2) {
            const int koff = kt*64 - qbase;       // 0 or 64
            const int q0 = w*16 + gid;
            #pragma unroll
            for (int nt = 0; nt < 8; nt++) {
                const int s0 = koff + nt*8 + 2*tg;
                if (s0     > q0)     sacc[nt][0] = -1e30f;
                if (s0 + 1 > q0)     sacc[nt][1] = -1e30f;
                if (s0     > q0 + 8) sacc[nt][2] = -1e30f;
                if (s0 + 1 > q0 + 8) sacc[nt][3] = -1e30f;
            }
        }

        // ---- online softmax in exp2 domain ----
        float t0 = -1e30f, t1 = -1e30f;
        #pragma unroll
        for (int nt = 0; nt < 8; nt++) {
            t0 = fmaxf(t0, fmaxf(sacc[nt][0], sacc[nt][1]));
            t1 = fmaxf(t1, fmaxf(sacc[nt][2], sacc[nt][3]));
        }
        t0 = fmaxf(t0, __shfl_xor_sync(0xffffffffu, t0, 1));
        t0 = fmaxf(t0, __shfl_xor_sync(0xffffffffu, t0, 2));
        t1 = fmaxf(t1, __shfl_xor_sync(0xffffffffu, t1, 1));
        t1 = fmaxf(t1, __shfl_xor_sync(0xffffffffu, t1, 2));

        const float mn0 = fmaxf(m0r, t0), mn1 = fmaxf(m1r, t1);
        const float cr0 = ex2((m0r - mn0) * FA_C1);
        const float cr1 = ex2((m1r - mn1) * FA_C1);
        m0r = mn0; m1r = mn1;
        l0 *= cr0; l1 *= cr1;
        #pragma unroll
        for (int d = 0; d < 8; d++) {
            oacc[d][0] *= cr0; oacc[d][1] *= cr0;
            oacc[d][2] *= cr1; oacc[d][3] *= cr1;
        }

        const float mc0 = mn0 * FA_C1, mc1 = mn1 * FA_C1;
        float s0 = 0.f, s1 = 0.f;
        #pragma unroll
        for (int nt = 0; nt < 8; nt++) {
            const float p0 = ex2(fmaf(sacc[nt][0], FA_C1, -mc0));
            const float p1 = ex2(fmaf(sacc[nt][1], FA_C1, -mc0));
            const float p2 = ex2(fmaf(sacc[nt][2], FA_C1, -mc1));
            const float p3 = ex2(fmaf(sacc[nt][3], FA_C1, -mc1));
            s0 += p0 + p1; s1 += p2 + p3;
            sacc[nt][0] = p0; sacc[nt][1] = p1; sacc[nt][2] = p2; sacc[nt][3] = p3;
        }
        s0 += __shfl_xor_sync(0xffffffffu, s0, 1);
        s0 += __shfl_xor_sync(0xffffffffu, s0, 2);
        s1 += __shfl_xor_sync(0xffffffffu, s1, 1);
        s1 += __shfl_xor_sync(0xffffffffu, s1, 2);
        l0 += s0; l1 += s1;

        // ---- O += P V ----
        const int lm = lane >> 3, lr = lane & 7;
        #pragma unroll
        for (int j = 0; j < 4; j++) {
            uint32_t a[4];
            a[0] = pack_h2(sacc[2*j  ][0], sacc[2*j  ][1]);
            a[1] = pack_h2(sacc[2*j  ][2], sacc[2*j  ][3]);
            a[2] = pack_h2(sacc[2*j+1][0], sacc[2*j+1][1]);
            a[3] = pack_h2(sacc[2*j+1][2], sacc[2*j+1][3]);
            #pragma unroll
            for (int dtp = 0; dtp < 4; dtp++) {
                const int s_a = j*16 + ((lm & 1) << 3) + lr;
                const int d_a = dtp*16 + ((lm >> 1) << 3);
                const uint32_t addr = vs_b + (uint32_t)(s_a*ALDH + d_a)*2;
                uint32_t b0, b1, b2, b3;
                LDSM_X4_TRANS(b0, b1, b2, b3, addr);
                MMA_F16(oacc[dtp*2],   a, b0, b1);
                MMA_F16(oacc[dtp*2+1], a, b2, b3);
            }
        }
        __syncthreads();

        if (kt + 2 < n_kt) load_kv(st, kt + 2);
    }

    // ---- normalize + write (fp16; feeds Wo GEMM) ----
    const float inv0 = 1.0f / l0, inv1 = 1.0f / l1;
    const int r0 = b*SS + qbase + w*16 + gid;
    __half* o0 = O + (size_t)r0*DM + h*DK;
    __half* o1 = o0 + (size_t)8*DM;
    #pragma unroll
    for (int dt = 0; dt < 8; dt++) {
        const int c = dt*8 + 2*tg;
        *(uint32_t*)(o0 + c) = pack_h2(oacc[dt][0]*inv0, oacc[dt][1]*inv0);
        *(uint32_t*)(o1 + c) = pack_h2(oacc[dt][2]*inv1, oacc[dt][3]*inv1);
    }
}

// ---------------------------------------------------------------------------
// Launch
// ---------------------------------------------------------------------------
extern "C" void kernel_launch(void* const* d_in, const int* in_sizes, int n_in,
                              void* d_out, int out_size)
{
    const float* x   = (const float*)d_in[0];
    const float* Wq  = (const float*)d_in[1];
    const float* bq  = (const float*)d_in[2];
    const float* Wk  = (const float*)d_in[3];
    const float* bk  = (const float*)d_in[4];
    const float* Wv  = (const float*)d_in[5];
    const float* bv  = (const float*)d_in[6];
    const float* Wo  = (const float*)d_in[7];
    const float* bo  = (const float*)d_in[8];
    const float* W1  = (const float*)d_in[9];
    const float* b1  = (const float*)d_in[10];
    const float* W2  = (const float*)d_in[11];
    const float* b2  = (const float*)d_in[12];
    const float* g1  = (const float*)d_in[13];
    const float* be1 = (const float*)d_in[14];
    const float* g2  = (const float*)d_in[15];
    const float* be2 = (const float*)d_in[16];
    float* out = (float*)d_out;

    __half *p_h, *p_qkv, *p_o, *p_ff;
    __half *p_wqkvt, *p_wot, *p_w1t, *p_w2t;
    float  *p_x1, *p_bqkv;
    cudaGetSymbolAddress((void**)&p_h,     g_h);
    cudaGetSymbolAddress((void**)&p_qkv,   g_qkv);
    cudaGetSymbolAddress((void**)&p_o,     g_o);
    cudaGetSymbolAddress((void**)&p_x1,    g_x1);
    cudaGetSymbolAddress((void**)&p_ff,    g_ff);
    cudaGetSymbolAddress((void**)&p_wqkvt, g_wqkvt);
    cudaGetSymbolAddress((void**)&p_wot,   g_wot);
    cudaGetSymbolAddress((void**)&p_w1t,   g_w1t);
    cudaGetSymbolAddress((void**)&p_w2t,   g_w2t);
    cudaGetSymbolAddress((void**)&p_bqkv,  g_bqkv);

    static bool attr_set = false;
    if (!attr_set) {
        cudaFuncSetAttribute(mma_gemm<false,false,true>,
                             cudaFuncAttributeMaxDynamicSharedMemorySize, GEMM_SMEM);
        cudaFuncSetAttribute(mma_gemm<false,true,false>,
                             cudaFuncAttributeMaxDynamicSharedMemorySize, GEMM_SMEM);
        cudaFuncSetAttribute(mma_gemm<true,false,true>,
                             cudaFuncAttributeMaxDynamicSharedMemorySize, GEMM_SMEM);
        cudaFuncSetAttribute(fa_kernel,
                             cudaFuncAttributeMaxDynamicSharedMemorySize, ATT_SMEM);
        attr_set = true;
    }

    const dim3 tblk(32, 8);
    // Weight prep: Wq/Wk/Wv into fused buffer + Wo; FFN transposes; bias concat
    transpose_round4<<<dim3(DM/32, DM/32, 4), tblk>>>(
        Wq, Wk, Wv, Wo, p_wqkvt, p_wot);
    transpose_round<<<dim3(DFF/32, DM/32),  tblk>>>(W1, p_w1t, DM,  DFF);
    transpose_round<<<dim3(DM/32,  DFF/32), tblk>>>(W2, p_w2t, DFF, DM);
    bias_concat<<<QKVS/256, 256>>>(bq, bk, bv, p_bqkv);

    const dim3 gQKV(QKVS/128, MROWS/128);  // (24, 64)
    const dim3 gD  (DM/128,   MROWS/128);  // (8, 64)
    const dim3 gF  (DFF/128,  MROWS/128);  // (32, 64)

    // 1. ln1(x) -> h (fp16)
    ln_kernel<<<MROWS, 256>>>(x, g1, be1, p_h);
    // 2. fused QKV projection (fp16 tensor pipe, N=3072)
    mma_gemm<false,false,true><<<gQKV, 256, GEMM_SMEM>>>(p_h, p_wqkvt, p_bqkv, nullptr, p_qkv, MROWS, QKVS, DM);
    // 3. causal attention (fp16 flash attention, 128-row q tiles)
    fa_kernel<<<dim3(SS/128, BB*HH), 256, ATT_SMEM>>>(p_qkv, p_o);
    // 4. output projection + residual(x) -> x1 (fp32)
    mma_gemm<false,true,false><<<gD, 256, GEMM_SMEM>>>(p_o, p_wot, bo, x, p_x1, MROWS, DM, DM);
    // 5. ln2(x1) -> h (fp16)
    ln_kernel<<<MROWS, 256>>>(p_x1, g2, be2, p_h);
    // 6. FFN up + ReLU (fp16 out)
    mma_gemm<true,false,true><<<gF, 256, GEMM_SMEM>>>(p_h, p_w1t, b1, nullptr, p_ff, MROWS, DFF, DM);
    // 7. FFN down + residual(x1) -> out (fp32)
    mma_gemm<false,true,false><<<gD, 256, GEMM_SMEM>>>(p_ff, p_w2t, b2, p_x1, out, MROWS, DM, DFF);
}

// round 9
// speedup vs baseline: 1.1180x; 1.0017x over previous
#include <cuda_runtime.h>
#include <cuda_fp16.h>
#include <math.h>
#include <stdint.h>

// Problem dimensions (fixed by the reference)
#define BB    4
#define SS    2048
#define DM    1024
#define HH    16
#define DK    64
#define DFF   4096
#define MROWS (BB*SS)          // 8192
#define QKVS  3072             // fused QKV row stride
#define LN_EPS 1e-5f

// ---------------------------------------------------------------------------
// Scratch (device globals; no allocations allowed)
// ---------------------------------------------------------------------------
__device__ __half g_h   [MROWS*DM];     // ln1 / ln2 output (fp16)
__device__ __half g_qkv [MROWS*QKVS];   // fused Q|K|V (fp16)
__device__ __half g_o   [MROWS*DM];     // attention output (fp16)
__device__ float  g_x1  [MROWS*DM];     // residual after attention (fp32)
__device__ __half g_ff  [MROWS*DFF];    // FFN hidden (fp16)
__device__ __half g_wqkvt[QKVS*DM];     // fused transposed weights [3072,1024]
__device__ __half g_wot [DM*DM];
__device__ __half g_w1t [DFF*DM];       // [4096,1024]
__device__ __half g_w2t [DM*DFF];       // [1024,4096]
__device__ float  g_bqkv[QKVS];         // fused bias

// ---------------------------------------------------------------------------
// Helpers
// ---------------------------------------------------------------------------
__device__ __forceinline__ uint32_t smem_u32(const void* p) {
    uint32_t a;
    asm("{ .reg .u64 t; cvta.to.shared.u64 t, %1; cvt.u32.u64 %0, t; }"
        : "=r"(a) : "l"(p));
    return a;
}

__device__ __forceinline__ uint32_t pack_h2(float lo, float hi) {
    __half2 h = __floats2half2_rn(lo, hi);
    return *reinterpret_cast<uint32_t*>(&h);
}

__device__ __forceinline__ float ex2(float x) {        // 2^x, MUFU.EX2
    float y;
    asm("ex2.approx.f32 %0, %1;" : "=f"(y) : "f"(x));
    return y;
}

#define CP_ASYNC16(dst, src) \
    asm volatile("cp.async.cg.shared.global [%0], [%1], 16;" :: "r"(dst), "l"(src))
#define CP_COMMIT()  asm volatile("cp.async.commit_group;" ::: "memory")
#define CP_WAIT(n)   asm volatile("cp.async.wait_group %0;" :: "n"(n) : "memory")

// m16n8k16 fp16 mma, fp32 accumulate
#define MMA_F16(d, a, b0, b1) \
    asm volatile("mma.sync.aligned.m16n8k16.row.col.f32.f16.f16.f32 " \
        "{%0,%1,%2,%3}, {%4,%5,%6,%7}, {%8,%9}, {%0,%1,%2,%3};" \
        : "+f"(d[0]), "+f"(d[1]), "+f"(d[2]), "+f"(d[3]) \
        : "r"(a[0]), "r"(a[1]), "r"(a[2]), "r"(a[3]), "r"(b0), "r"(b1))

#define LDSM_X4(r0, r1, r2, r3, addr) \
    asm volatile("ldmatrix.sync.aligned.m8n8.x4.shared.b16 {%0,%1,%2,%3}, [%4];" \
        : "=r"(r0), "=r"(r1), "=r"(r2), "=r"(r3) : "r"(addr))

#define LDSM_X2(r0, r1, addr) \
    asm volatile("ldmatrix.sync.aligned.m8n8.x2.shared.b16 {%0,%1}, [%2];" \
        : "=r"(r0), "=r"(r1) : "r"(addr))

#define LDSM_X4_TRANS(r0, r1, r2, r3, addr) \
    asm volatile("ldmatrix.sync.aligned.m8n8.x4.trans.shared.b16 {%0,%1,%2,%3}, [%4];" \
        : "=r"(r0), "=r"(r1), "=r"(r2), "=r"(r3) : "r"(addr))

// ---------------------------------------------------------------------------
// LayerNorm -> fp16 output
// ---------------------------------------------------------------------------
__global__ __launch_bounds__(256) void ln_kernel(
    const float* __restrict__ X, const float* __restrict__ gamma,
    const float* __restrict__ beta, __half* __restrict__ out)
{
    const int row = blockIdx.x;
    const int t   = threadIdx.x;
    const float4 v = ((const float4*)(X + (size_t)row*DM))[t];

    float s  = v.x + v.y + v.z + v.w;
    float ss = v.x*v.x + v.y*v.y + v.z*v.z + v.w*v.w;

    #pragma unroll
    for (int o = 16; o > 0; o >>= 1) {
        s  += __shfl_xor_sync(0xffffffffu, s,  o);
        ss += __shfl_xor_sync(0xffffffffu, ss, o);
    }
    __shared__ float sh_s[8], sh_ss[8];
    const int w = t >> 5, lane = t & 31;
    if (lane == 0) { sh_s[w] = s; sh_ss[w] = ss; }
    __syncthreads();
    if (w == 0) {
        s  = (lane < 8) ? sh_s[lane]  : 0.f;
        ss = (lane < 8) ? sh_ss[lane] : 0.f;
        #pragma unroll
        for (int o = 4; o > 0; o >>= 1) {
            s  += __shfl_xor_sync(0xffffffffu, s,  o);
            ss += __shfl_xor_sync(0xffffffffu, ss, o);
        }
        if (lane == 0) { sh_s[0] = s; sh_ss[0] = ss; }
    }
    __syncthreads();
    s = sh_s[0]; ss = sh_ss[0];

    const float mu   = s * (1.0f / DM);
    const float var  = ss * (1.0f / DM) - mu*mu;
    const float rstd = rsqrtf(var + LN_EPS);

    const float4 g4 = ((const float4*)gamma)[t];
    const float4 b4 = ((const float4*)beta)[t];
    uint2 st;
    st.x = pack_h2((v.x - mu)*rstd*g4.x + b4.x, (v.y - mu)*rstd*g4.y + b4.y);
    st.y = pack_h2((v.z - mu)*rstd*g4.z + b4.z, (v.w - mu)*rstd*g4.w + b4.w);
    ((uint2*)(out + (size_t)row*DM))[t] = st;
}

// ---------------------------------------------------------------------------
// Weight transpose + fp16 rounding: W[K,N] (f32) -> Wt[N,K] (f16)
// ---------------------------------------------------------------------------
__global__ __launch_bounds__(256) void transpose_round(
    const float* __restrict__ W, __half* __restrict__ Wt, int K, int N)
{
    __shared__ float tile[32][33];
    const int tx = threadIdx.x, ty = threadIdx.y;
    const int n0 = blockIdx.x * 32, k0 = blockIdx.y * 32;
    #pragma unroll
    for (int i = ty; i < 32; i += 8)
        tile[i][tx] = W[(size_t)(k0 + i)*N + n0 + tx];
    __syncthreads();
    #pragma unroll
    for (int i = ty; i < 32; i += 8)
        Wt[(size_t)(n0 + i)*K + k0 + tx] = __float2half_rn(tile[tx][i]);
}

// Fused prep: z=0..3 -> DMxDM transposes (Wq/Wk/Wv into fused buffer, Wo),
//             z=4    -> QKV bias concat (first 12 x-blocks, y==0)
__global__ __launch_bounds__(256) void transpose_round4(
    const float* __restrict__ W0, const float* __restrict__ W1,
    const float* __restrict__ W2, const float* __restrict__ W3,
    __half* __restrict__ Tqkv, __half* __restrict__ To,
    const float* __restrict__ bq, const float* __restrict__ bk,
    const float* __restrict__ bv, float* __restrict__ bqkv)
{
    if (blockIdx.z == 4) {
        if (blockIdx.y == 0 && blockIdx.x < 12) {
            const int i = blockIdx.x*256 + threadIdx.y*32 + threadIdx.x;
            if (i < DM)        bqkv[i] = bq[i];
            else if (i < 2*DM) bqkv[i] = bk[i - DM];
            else               bqkv[i] = bv[i - 2*DM];
        }
        return;
    }
    const float* W; __half* T;
    switch (blockIdx.z) {
        case 0: W = W0; T = Tqkv;             break;
        case 1: W = W1; T = Tqkv + DM*DM;     break;
        case 2: W = W2; T = Tqkv + 2*DM*DM;   break;
        default: W = W3; T = To;              break;
    }
    __shared__ float tile[32][33];
    const int tx = threadIdx.x, ty = threadIdx.y;
    const int n0 = blockIdx.x * 32, k0 = blockIdx.y * 32;
    #pragma unroll
    for (int i = ty; i < 32; i += 8)
        tile[i][tx] = W[(size_t)(k0 + i)*DM + n0 + tx];
    __syncthreads();
    #pragma unroll
    for (int i = ty; i < 32; i += 8)
        T[(size_t)(n0 + i)*DM + k0 + tx] = __float2half_rn(tile[tx][i]);
}

// ---------------------------------------------------------------------------
// fp16 mma.sync GEMM: C[M,N] = A[M,K] @ Bt[N,K]^T + bias (+relu)(+res)
// 128x128 CTA tile, BK=64, 3-stage cp.async, 256 threads (8 warps, 2x4),
// warp tile 64x32, ldmatrix fragments, 2 CTAs/SM. ONE barrier per chunk:
// the prefetch issued after the top sync writes stage (i-1)%3, which every
// warp finished reading before passing that sync.
// ---------------------------------------------------------------------------
#define GST    3
#define LDH    72
#define TILE_H (128*LDH)                 // halves per tile (9216)
#define STAGE_BYTES (2*TILE_H*2)         // A + B = 36864 B
#define GEMM_SMEM (GST*STAGE_BYTES)      // 110592 B

template<bool RELU, bool RES, bool HALF_OUT>
__global__ __launch_bounds__(256, 2) void mma_gemm(
    const __half* __restrict__ A, const __half* __restrict__ Bt,
    const float* __restrict__ bias, const float* __restrict__ res,
    void* __restrict__ Cv, int M, int N, int K)
{
    extern __shared__ char smc[];
    const uint32_t sm_b = smem_u32(smc);

    const int tid  = threadIdx.x;
    const int lane = tid & 31, wid = tid >> 5;
    const int wm = wid >> 2, wn = wid & 3;        // 2 x 4 warp grid
    const int gid = lane >> 2, tg = lane & 3;
    const int bx = blockIdx.x, by = blockIdx.y;

    const __half* Ab = A  + (size_t)by * 128 * K;
    const __half* Bb = Bt + (size_t)bx * 128 * K;
    const int nchunks = K >> 6;                   // K/64

    // ldmatrix per-lane offsets (bytes) within a stage's A / B tile
    const int la7 = lane & 7;
    uint32_t offA[4], offB[4];
    {
        const int arow = la7 + ((lane >> 3) & 1) * 8;
        const int acol = (lane >> 4) * 8;
        #pragma unroll
        for (int mt = 0; mt < 4; mt++)
            offA[mt] = (uint32_t)(((wm*64 + mt*16 + arow)*LDH + acol) * 2);
        const int bcol = ((lane >> 3) & 1) * 8;
        #pragma unroll
        for (int nt = 0; nt < 4; nt++)
            offB[nt] = (uint32_t)(((wn*32 + nt*8 + la7)*LDH + bcol) * 2);
    }

    // Stage loader: 2 tiles x 128 rows x 64 halves (8x16B per row)
    auto load_stage = [&](int st, int kt) {
        const uint32_t a_dst = sm_b + (uint32_t)st*STAGE_BYTES;
        const uint32_t b_dst = a_dst + TILE_H*2;
        const __half* as = Ab + (size_t)kt*64;
        const __half* bs = Bb + (size_t)kt*64;
        #pragma unroll
        for (int it = 0; it < 4; it++) {
            const int idx = it*256 + tid;
            const int r = idx >> 3, c8 = idx & 7;
            const uint32_t off = (uint32_t)(r*144 + c8*16);
            CP_ASYNC16(a_dst + off, as + (size_t)r*K + c8*8);
            CP_ASYNC16(b_dst + off, bs + (size_t)r*K + c8*8);
        }
        CP_COMMIT();
    };

    float acc[4][4][4];
    #pragma unroll
    for (int i = 0; i < 4; i++)
        #pragma unroll
        for (int j = 0; j < 4; j++)
            #pragma unroll
            for (int k = 0; k < 4; k++) acc[i][j][k] = 0.f;

    load_stage(0, 0);
    if (nchunks > 1) load_stage(1, 1);

    for (int i = 0; i < nchunks; i++) {
        const int st = i % GST;
        if (i + 1 < nchunks) { CP_WAIT(1); } else { CP_WAIT(0); }
        __syncthreads();

        if (i + (GST-1) < nchunks)
            load_stage((i + GST - 1) % GST, i + GST - 1);

        const uint32_t aBase = sm_b + (uint32_t)st*STAGE_BYTES;
        const uint32_t bBase = aBase + TILE_H*2;

        #pragma unroll
        for (int kk = 0; kk < 4; kk++) {
            uint32_t a[4][4], b[4][2];
            #pragma unroll
            for (int mt = 0; mt < 4; mt++)
                LDSM_X4(a[mt][0], a[mt][1], a[mt][2], a[mt][3],
                        aBase + offA[mt] + kk*32);
            #pragma unroll
            for (int nt = 0; nt < 4; nt++)
                LDSM_X2(b[nt][0], b[nt][1], bBase + offB[nt] + kk*32);
            #pragma unroll
            for (int mt = 0; mt < 4; mt++)
                #pragma unroll
                for (int nt = 0; nt < 4; nt++)
                    MMA_F16(acc[mt][nt], a[mt], b[nt][0], b[nt][1]);
        }
        // no trailing barrier: next iteration's top sync protects stage reuse
    }

    // Epilogue
    #pragma unroll
    for (int mt = 0; mt < 4; mt++) {
        #pragma unroll
        for (int nt = 0; nt < 4; nt++) {
            const int r0 = by*128 + wm*64 + mt*16 + gid;
            const int c  = bx*128 + wn*32 + nt*8 + tg*2;
            const float2 b2 = *(const float2*)(bias + c);
            #pragma unroll
            for (int half_i = 0; half_i < 2; half_i++) {
                const int r = r0 + half_i*8;
                float ox = acc[mt][nt][half_i*2+0] + b2.x;
                float oy = acc[mt][nt][half_i*2+1] + b2.y;
                if (RELU) { ox = fmaxf(ox, 0.f); oy = fmaxf(oy, 0.f); }
                if (RES) {
                    const float2 r2 = *(const float2*)(res + (size_t)r*N + c);
                    ox += r2.x; oy += r2.y;
                }
                if (HALF_OUT) {
                    *(uint32_t*)((__half*)Cv + (size_t)r*N + c) = pack_h2(ox, oy);
                } else {
                    float2 o; o.x = ox; o.y = oy;
                    *(float2*)((float*)Cv + (size_t)r*N + c) = o;
                }
            }
        }
    }
}

// ---------------------------------------------------------------------------
// fp16 tensor-core causal flash attention, d_k=64, fused QKV input.
// CTA: 256 threads (8 warps), 128 q rows (16/warp), 64-key KV tiles,
// 3-stage cp.async ring, ONE barrier per KV tile (prefetch after top sync
// writes the stage consumed at iter kt-1).
// ---------------------------------------------------------------------------
#define ALDH 72
#define ATILE_B (64*ALDH*2)               // 9216 B per 64x64 half tile
#define ATT_SMEM (6*ATILE_B)              // 3 stages x (K+V) = 55296 B
#define FA_C1 0.1803368801111204f          // log2(e)/8

__global__ __launch_bounds__(256) void fa_kernel(
    const __half* __restrict__ QKV, __half* __restrict__ O)
{
    extern __shared__ char fsc[];
    const int tid  = threadIdx.x;
    const int lane = tid & 31, w = tid >> 5;      // 8 warps
    const int gid  = lane >> 2, tg = lane & 3;
    const int qt   = (int)gridDim.x - 1 - (int)blockIdx.x;   // big tiles first
    const int bh   = blockIdx.y;
    const int b    = bh >> 4, h = bh & 15;
    const int qbase = qt * 128;
    const int n_kt  = 2*qt + 2;                   // 64-key tiles to process

    __half* Ks[3] = { (__half*)fsc,                 (__half*)(fsc + 2*ATILE_B),
                      (__half*)(fsc + 4*ATILE_B) };
    __half* Vs[3] = { (__half*)(fsc + ATILE_B),     (__half*)(fsc + 3*ATILE_B),
                      (__half*)(fsc + 5*ATILE_B) };

    // 64-row tile loader (256 threads, 2 chunks each)
    auto load_tile = [&](__half* dst, const __half* src) {
        const uint32_t d0 = smem_u32(dst);
        #pragma unroll
        for (int i = 0; i < 2; i++) {
            const int idx = i*256 + tid;
            const int r = idx >> 3, c8 = idx & 7;
            CP_ASYNC16(d0 + (uint32_t)(r*144 + c8*16), src + (size_t)r*QKVS + c8*8);
        }
    };

    const __half* Kg = QKV + (size_t)(b*SS)*QKVS + DM + h*DK;
    const __half* Vg = QKV + (size_t)(b*SS)*QKVS + 2*DM + h*DK;
    auto load_kv = [&](int st, int kt) {
        load_tile(Ks[st], Kg + (size_t)(kt*64)*QKVS);
        load_tile(Vs[st], Vg + (size_t)(kt*64)*QKVS);
        CP_COMMIT();
    };

    // ldmatrix per-lane offsets
    const int la7 = lane & 7;
    const uint32_t offQ = (uint32_t)(((w*16 + la7 + ((lane>>3)&1)*8)*ALDH
                                     + (lane>>4)*8) * 2);
    uint32_t offK[8];
    #pragma unroll
    for (int nt = 0; nt < 8; nt++)
        offK[nt] = (uint32_t)(((nt*8 + la7)*ALDH + ((lane>>3)&1)*8) * 2);

    // --- Stage 128-row Q tile through smem (uses Ks[0]+Vs[0] region) ---
    {
        const uint32_t d0 = smem_u32(fsc);
        const __half* qsrc = QKV + (size_t)(b*SS + qbase)*QKVS + h*DK;
        #pragma unroll
        for (int i = 0; i < 4; i++) {
            const int idx = i*256 + tid;
            const int r = idx >> 3, c8 = idx & 7;
            CP_ASYNC16(d0 + (uint32_t)(r*144 + c8*16), qsrc + (size_t)r*QKVS + c8*8);
        }
        CP_COMMIT();
        CP_WAIT(0);
    }
    __syncthreads();

    uint32_t qf[4][4];
    {
        const uint32_t qsB = smem_u32(fsc);
        #pragma unroll
        for (int kk = 0; kk < 4; kk++)
            LDSM_X4(qf[kk][0], qf[kk][1], qf[kk][2], qf[kk][3],
                    qsB + offQ + kk*32);
    }
    __syncthreads();

    load_kv(0, 0);
    if (n_kt > 1) load_kv(1, 1);

    float oacc[8][4];
    #pragma unroll
    for (int d = 0; d < 8; d++) {
        oacc[d][0] = 0.f; oacc[d][1] = 0.f; oacc[d][2] = 0.f; oacc[d][3] = 0.f;
    }
    float m0r = -INFINITY, m1r = -INFINITY, l0 = 0.f, l1 = 0.f;

    for (int kt = 0; kt < n_kt; kt++) {
        const int st = kt % 3;
        if (kt + 1 < n_kt) { CP_WAIT(1); } else { CP_WAIT(0); }
        __syncthreads();

        if (kt + 2 < n_kt) load_kv((kt + 2) % 3, kt + 2);

        const uint32_t ks_b = smem_u32(Ks[st]);
        const uint32_t vs_b = smem_u32(Vs[st]);

        // ---- S = Q K^T (unscaled) ----
        float sacc[8][4];
        #pragma unroll
        for (int nt = 0; nt < 8; nt++) {
            sacc[nt][0] = 0.f; sacc[nt][1] = 0.f; sacc[nt][2] = 0.f; sacc[nt][3] = 0.f;
        }
        #pragma unroll
        for (int kk = 0; kk < 4; kk++) {
            #pragma unroll
            for (int nt = 0; nt < 8; nt++) {
                uint32_t b0, b1;
                LDSM_X2(b0, b1, ks_b + offK[nt] + kk*32);
                MMA_F16(sacc[nt], qf[kk], b0, b1);
            }
        }

        // ---- causal mask (last two tiles only) ----
        if (kt >= n_kt - 2) {
            const int koff = kt*64 - qbase;       // 0 or 64
            const int q0 = w*16 + gid;
            #pragma unroll
            for (int nt = 0; nt < 8; nt++) {
                const int s0 = koff + nt*8 + 2*tg;
                if (s0     > q0)     sacc[nt][0] = -1e30f;
                if (s0 + 1 > q0)     sacc[nt][1] = -1e30f;
                if (s0     > q0 + 8) sacc[nt][2] = -1e30f;
                if (s0 + 1 > q0 + 8) sacc[nt][3] = -1e30f;
            }
        }

        // ---- online softmax in exp2 domain ----
        float t0 = -1e30f, t1 = -1e30f;
        #pragma unroll
        for (int nt = 0; nt < 8; nt++) {
            t0 = fmaxf(t0, fmaxf(sacc[nt][0], sacc[nt][1]));
            t1 = fmaxf(t1, fmaxf(sacc[nt][2], sacc[nt][3]));
        }
        t0 = fmaxf(t0, __shfl_xor_sync(0xffffffffu, t0, 1));
        t0 = fmaxf(t0, __shfl_xor_sync(0xffffffffu, t0, 2));
        t1 = fmaxf(t1, __shfl_xor_sync(0xffffffffu, t1, 1));
        t1 = fmaxf(t1, __shfl_xor_sync(0xffffffffu, t1, 2));

        const float mn0 = fmaxf(m0r, t0), mn1 = fmaxf(m1r, t1);
        const float cr0 = ex2((m0r - mn0) * FA_C1);
        const float cr1 = ex2((m1r - mn1) * FA_C1);
        m0r = mn0; m1r = mn1;
        l0 *= cr0; l1 *= cr1;
        #pragma unroll
        for (int d = 0; d < 8; d++) {
            oacc[d][0] *= cr0; oacc[d][1] *= cr0;
            oacc[d][2] *= cr1; oacc[d][3] *= cr1;
        }

        const float mc0 = mn0 * FA_C1, mc1 = mn1 * FA_C1;
        float s0 = 0.f, s1 = 0.f;
        #pragma unroll
        for (int nt = 0; nt < 8; nt++) {
            const float p0 = ex2(fmaf(sacc[nt][0], FA_C1, -mc0));
            const float p1 = ex2(fmaf(sacc[nt][1], FA_C1, -mc0));
            const float p2 = ex2(fmaf(sacc[nt][2], FA_C1, -mc1));
            const float p3 = ex2(fmaf(sacc[nt][3], FA_C1, -mc1));
            s0 += p0 + p1; s1 += p2 + p3;
            sacc[nt][0] = p0; sacc[nt][1] = p1; sacc[nt][2] = p2; sacc[nt][3] = p3;
        }
        s0 += __shfl_xor_sync(0xffffffffu, s0, 1);
        s0 += __shfl_xor_sync(0xffffffffu, s0, 2);
        s1 += __shfl_xor_sync(0xffffffffu, s1, 1);
        s1 += __shfl_xor_sync(0xffffffffu, s1, 2);
        l0 += s0; l1 += s1;

        // ---- O += P V ----
        const int lm = lane >> 3, lr = lane & 7;
        #pragma unroll
        for (int j = 0; j < 4; j++) {
            uint32_t a[4];
            a[0] = pack_h2(sacc[2*j  ][0], sacc[2*j  ][1]);
            a[1] = pack_h2(sacc[2*j  ][2], sacc[2*j  ][3]);
            a[2] = pack_h2(sacc[2*j+1][0], sacc[2*j+1][1]);
            a[3] = pack_h2(sacc[2*j+1][2], sacc[2*j+1][3]);
            #pragma unroll
            for (int dtp = 0; dtp < 4; dtp++) {
                const int s_a = j*16 + ((lm & 1) << 3) + lr;
                const int d_a = dtp*16 + ((lm >> 1) << 3);
                const uint32_t addr = vs_b + (uint32_t)(s_a*ALDH + d_a)*2;
                uint32_t b0, b1, b2, b3;
                LDSM_X4_TRANS(b0, b1, b2, b3, addr);
                MMA_F16(oacc[dtp*2],   a, b0, b1);
                MMA_F16(oacc[dtp*2+1], a, b2, b3);
            }
        }
        // no trailing barrier: next iteration's top sync protects stage reuse
    }

    // ---- normalize + write (fp16; feeds Wo GEMM) ----
    const float inv0 = 1.0f / l0, inv1 = 1.0f / l1;
    const int r0 = b*SS + qbase + w*16 + gid;
    __half* o0 = O + (size_t)r0*DM + h*DK;
    __half* o1 = o0 + (size_t)8*DM;
    #pragma unroll
    for (int dt = 0; dt < 8; dt++) {
        const int c = dt*8 + 2*tg;
        *(uint32_t*)(o0 + c) = pack_h2(oacc[dt][0]*inv0, oacc[dt][1]*inv0);
        *(uint32_t*)(o1 + c) = pack_h2(oacc[dt][2]*inv1, oacc[dt][3]*inv1);
    }
}

// ---------------------------------------------------------------------------
// Launch
// ---------------------------------------------------------------------------
extern "C" void kernel_launch(void* const* d_in, const int* in_sizes, int n_in,
                              void* d_out, int out_size)
{
    const float* x   = (const float*)d_in[0];
    const float* Wq  = (const float*)d_in[1];
    const float* bq  = (const float*)d_in[2];
    const float* Wk  = (const float*)d_in[3];
    const float* bk  = (const float*)d_in[4];
    const float* Wv  = (const float*)d_in[5];
    const float* bv  = (const float*)d_in[6];
    const float* Wo  = (const float*)d_in[7];
    const float* bo  = (const float*)d_in[8];
    const float* W1  = (const float*)d_in[9];
    const float* b1  = (const float*)d_in[10];
    const float* W2  = (const float*)d_in[11];
    const float* b2  = (const float*)d_in[12];
    const float* g1  = (const float*)d_in[13];
    const float* be1 = (const float*)d_in[14];
    const float* g2  = (const float*)d_in[15];
    const float* be2 = (const float*)d_in[16];
    float* out = (float*)d_out;

    __half *p_h, *p_qkv, *p_o, *p_ff;
    __half *p_wqkvt, *p_wot, *p_w1t, *p_w2t;
    float  *p_x1, *p_bqkv;
    cudaGetSymbolAddress((void**)&p_h,     g_h);
    cudaGetSymbolAddress((void**)&p_qkv,   g_qkv);
    cudaGetSymbolAddress((void**)&p_o,     g_o);
    cudaGetSymbolAddress((void**)&p_x1,    g_x1);
    cudaGetSymbolAddress((void**)&p_ff,    g_ff);
    cudaGetSymbolAddress((void**)&p_wqkvt, g_wqkvt);
    cudaGetSymbolAddress((void**)&p_wot,   g_wot);
    cudaGetSymbolAddress((void**)&p_w1t,   g_w1t);
    cudaGetSymbolAddress((void**)&p_w2t,   g_w2t);
    cudaGetSymbolAddress((void**)&p_bqkv,  g_bqkv);

    static bool attr_set = false;
    if (!attr_set) {
        cudaFuncSetAttribute(mma_gemm<false,false,true>,
                             cudaFuncAttributeMaxDynamicSharedMemorySize, GEMM_SMEM);
        cudaFuncSetAttribute(mma_gemm<false,true,false>,
                             cudaFuncAttributeMaxDynamicSharedMemorySize, GEMM_SMEM);
        cudaFuncSetAttribute(mma_gemm<true,false,true>,
                             cudaFuncAttributeMaxDynamicSharedMemorySize, GEMM_SMEM);
        cudaFuncSetAttribute(fa_kernel,
                             cudaFuncAttributeMaxDynamicSharedMemorySize, ATT_SMEM);
        attr_set = true;
    }

    const dim3 tblk(32, 8);
    // Weight prep: Wq/Wk/Wv into fused buffer + Wo + bias concat (one launch),
    // then the two FFN transposes
    transpose_round4<<<dim3(DM/32, DM/32, 5), tblk>>>(
        Wq, Wk, Wv, Wo, p_wqkvt, p_wot, bq, bk, bv, p_bqkv);
    transpose_round<<<dim3(DFF/32, DM/32),  tblk>>>(W1, p_w1t, DM,  DFF);
    transpose_round<<<dim3(DM/32,  DFF/32), tblk>>>(W2, p_w2t, DFF, DM);

    const dim3 gQKV(QKVS/128, MROWS/128);  // (24, 64)
    const dim3 gD  (DM/128,   MROWS/128);  // (8, 64)
    const dim3 gF  (DFF/128,  MROWS/128);  // (32, 64)

    // 1. ln1(x) -> h (fp16)
    ln_kernel<<<MROWS, 256>>>(x, g1, be1, p_h);
    // 2. fused QKV projection (fp16 tensor pipe, N=3072)
    mma_gemm<false,false,true><<<gQKV, 256, GEMM_SMEM>>>(p_h, p_wqkvt, p_bqkv, nullptr, p_qkv, MROWS, QKVS, DM);
    // 3. causal attention (fp16 flash attention, 128-row q tiles)
    fa_kernel<<<dim3(SS/128, BB*HH), 256, ATT_SMEM>>>(p_qkv, p_o);
    // 4. output projection + residual(x) -> x1 (fp32)
    mma_gemm<false,true,false><<<gD, 256, GEMM_SMEM>>>(p_o, p_wot, bo, x, p_x1, MROWS, DM, DM);
    // 5. ln2(x1) -> h (fp16)
    ln_kernel<<<MROWS, 256>>>(p_x1, g2, be2, p_h);
    // 6. FFN up + ReLU (fp16 out)
    mma_gemm<true,false,true><<<gF, 256, GEMM_SMEM>>>(p_h, p_w1t, b1, nullptr, p_ff, MROWS, DFF, DM);
    // 7. FFN down + residual(x1) -> out (fp32)
    mma_gemm<false,true,false><<<gD, 256, GEMM_SMEM>>>(p_ff, p_w2t, b2, p_x1, out, MROWS, DM, DFF);
}

// round 10
// speedup vs baseline: 1.1425x; 1.0219x over previous
#include <cuda_runtime.h>
#include <cuda_fp16.h>
#include <math.h>
#include <stdint.h>

// Problem dimensions (fixed by the reference)
#define BB    4
#define SS    2048
#define DM    1024
#define HH    16
#define DK    64
#define DFF   4096
#define MROWS (BB*SS)          // 8192
#define QKVS  3072             // fused QKV row stride
#define LN_EPS 1e-5f

// ---------------------------------------------------------------------------
// Scratch (device globals; no allocations allowed)
// ---------------------------------------------------------------------------
__device__ __half g_h   [MROWS*DM];     // ln1 / ln2 output (fp16)
__device__ __half g_qkv [MROWS*QKVS];   // fused Q|K|V (fp16)
__device__ __half g_o   [MROWS*DM];     // attention output (fp16)
__device__ float  g_x1  [MROWS*DM];     // residual after attention (fp32)
__device__ __half g_ff  [MROWS*DFF];    // FFN hidden (fp16)
__device__ __half g_wqkvt[QKVS*DM];     // fused transposed weights [3072,1024]
__device__ __half g_wot [DM*DM];
__device__ __half g_w1t [DFF*DM];       // [4096,1024]
__device__ __half g_w2t [DM*DFF];       // [1024,4096]
__device__ float  g_bqkv[QKVS];         // fused bias

// ---------------------------------------------------------------------------
// Helpers
// ---------------------------------------------------------------------------
__device__ __forceinline__ uint32_t smem_u32(const void* p) {
    uint32_t a;
    asm("{ .reg .u64 t; cvta.to.shared.u64 t, %1; cvt.u32.u64 %0, t; }"
        : "=r"(a) : "l"(p));
    return a;
}

__device__ __forceinline__ uint32_t pack_h2(float lo, float hi) {
    __half2 h = __floats2half2_rn(lo, hi);
    return *reinterpret_cast<uint32_t*>(&h);
}

__device__ __forceinline__ float ex2(float x) {        // 2^x, MUFU.EX2
    float y;
    asm("ex2.approx.f32 %0, %1;" : "=f"(y) : "f"(x));
    return y;
}

#define CP_ASYNC16(dst, src) \
    asm volatile("cp.async.cg.shared.global [%0], [%1], 16;" :: "r"(dst), "l"(src))
#define CP_COMMIT()  asm volatile("cp.async.commit_group;" ::: "memory")
#define CP_WAIT(n)   asm volatile("cp.async.wait_group %0;" :: "n"(n) : "memory")

// m16n8k16 fp16 mma, fp32 accumulate
#define MMA_F16(d, a, b0, b1) \
    asm volatile("mma.sync.aligned.m16n8k16.row.col.f32.f16.f16.f32 " \
        "{%0,%1,%2,%3}, {%4,%5,%6,%7}, {%8,%9}, {%0,%1,%2,%3};" \
        : "+f"(d[0]), "+f"(d[1]), "+f"(d[2]), "+f"(d[3]) \
        : "r"(a[0]), "r"(a[1]), "r"(a[2]), "r"(a[3]), "r"(b0), "r"(b1))

#define LDSM_X4(r0, r1, r2, r3, addr) \
    asm volatile("ldmatrix.sync.aligned.m8n8.x4.shared.b16 {%0,%1,%2,%3}, [%4];" \
        : "=r"(r0), "=r"(r1), "=r"(r2), "=r"(r3) : "r"(addr))

#define LDSM_X2(r0, r1, addr) \
    asm volatile("ldmatrix.sync.aligned.m8n8.x2.shared.b16 {%0,%1}, [%2];" \
        : "=r"(r0), "=r"(r1) : "r"(addr))

#define LDSM_X4_TRANS(r0, r1, r2, r3, addr) \
    asm volatile("ldmatrix.sync.aligned.m8n8.x4.trans.shared.b16 {%0,%1,%2,%3}, [%4];" \
        : "=r"(r0), "=r"(r1), "=r"(r2), "=r"(r3) : "r"(addr))

// ---------------------------------------------------------------------------
// LayerNorm -> fp16, warp-per-row (8 rows per 256-thread block, no barriers)
// ---------------------------------------------------------------------------
__global__ __launch_bounds__(256) void ln_kernel(
    const float* __restrict__ X, const float* __restrict__ gamma,
    const float* __restrict__ beta, __half* __restrict__ out)
{
    const int t = threadIdx.x, lane = t & 31, w = t >> 5;
    const int row = blockIdx.x*8 + w;

    cudaGridDependencySynchronize();

    const float4* Xr = (const float4*)(X + (size_t)row*DM);
    float4 v[8];
    float s = 0.f, ss = 0.f;
    #pragma unroll
    for (int i = 0; i < 8; i++) {
        v[i] = Xr[lane + i*32];
        s  += v[i].x + v[i].y + v[i].z + v[i].w;
        ss += v[i].x*v[i].x + v[i].y*v[i].y + v[i].z*v[i].z + v[i].w*v[i].w;
    }
    #pragma unroll
    for (int o = 16; o > 0; o >>= 1) {
        s  += __shfl_xor_sync(0xffffffffu, s,  o);
        ss += __shfl_xor_sync(0xffffffffu, ss, o);
    }
    const float mu   = s * (1.0f / DM);
    const float var  = ss * (1.0f / DM) - mu*mu;
    const float rstd = rsqrtf(var + LN_EPS);

    const float4* G  = (const float4*)gamma;
    const float4* Bt = (const float4*)beta;
    uint2* Or = (uint2*)(out + (size_t)row*DM);
    #pragma unroll
    for (int i = 0; i < 8; i++) {
        const float4 g4 = G[lane + i*32];
        const float4 b4 = Bt[lane + i*32];
        uint2 st;
        st.x = pack_h2((v[i].x - mu)*rstd*g4.x + b4.x,
                       (v[i].y - mu)*rstd*g4.y + b4.y);
        st.y = pack_h2((v[i].z - mu)*rstd*g4.z + b4.z,
                       (v[i].w - mu)*rstd*g4.w + b4.w);
        Or[lane + i*32] = st;
    }
}

// ---------------------------------------------------------------------------
// Single prep kernel: z=0..5 -> transpose+round of Wq/Wk/Wv/Wo/W1/W2,
// bias concat folded into z=0 blocks 1024..1035. Grid (4096,1,6), block 256.
// ---------------------------------------------------------------------------
__global__ __launch_bounds__(256) void prep_kernel(
    const float* __restrict__ Wq, const float* __restrict__ Wk,
    const float* __restrict__ Wv, const float* __restrict__ Wo,
    const float* __restrict__ W1, const float* __restrict__ W2,
    __half* __restrict__ Tqkv, __half* __restrict__ To,
    __half* __restrict__ T1, __half* __restrict__ T2,
    const float* __restrict__ bq, const float* __restrict__ bk,
    const float* __restrict__ bv, float* __restrict__ bqkv)
{
    const int z = blockIdx.z;
    const float* W; __half* T; int K, N;
    switch (z) {
        case 0:  W = Wq; T = Tqkv;           K = DM;  N = DM;  break;
        case 1:  W = Wk; T = Tqkv + DM*DM;   K = DM;  N = DM;  break;
        case 2:  W = Wv; T = Tqkv + 2*DM*DM; K = DM;  N = DM;  break;
        case 3:  W = Wo; T = To;             K = DM;  N = DM;  break;
        case 4:  W = W1; T = T1;             K = DM;  N = DFF; break;
        default: W = W2; T = T2;             K = DFF; N = DM;  break;
    }
    // bias concat on z=0 blocks 1024..1035
    if (z == 0 && blockIdx.x >= 1024) {
        if (blockIdx.x < 1036) {
            const int i = (blockIdx.x - 1024)*256 + threadIdx.x;
            if (i < DM)        bqkv[i] = bq[i];
            else if (i < 2*DM) bqkv[i] = bk[i - DM];
            else               bqkv[i] = bv[i - 2*DM];
        }
        return;
    }
    const int nblk = N >> 5;
    const int bx = blockIdx.x % nblk, byk = blockIdx.x / nblk;
    if (byk >= (K >> 5)) return;

    __shared__ float tile[32][33];
    const int tx = threadIdx.x & 31, ty = threadIdx.x >> 5;
    const int n0 = bx*32, k0 = byk*32;
    #pragma unroll
    for (int i = ty; i < 32; i += 8)
        tile[i][tx] = W[(size_t)(k0 + i)*N + n0 + tx];
    __syncthreads();
    #pragma unroll
    for (int i = ty; i < 32; i += 8)
        T[(size_t)(n0 + i)*K + k0 + tx] = __float2half_rn(tile[tx][i]);
}

// ---------------------------------------------------------------------------
// fp16 mma.sync GEMM: C[M,N] = A[M,K] @ Bt[N,K]^T + bias (+relu)(+res)
// 128x128 CTA tile, BK=64, 3-stage cp.async, 256 threads (8 warps, 2x4),
// warp tile 64x32, ldmatrix fragments, 2 CTAs/SM, one barrier per chunk.
// ---------------------------------------------------------------------------
#define GST    3
#define LDH    72
#define TILE_H (128*LDH)                 // halves per tile (9216)
#define STAGE_BYTES (2*TILE_H*2)         // A + B = 36864 B
#define GEMM_SMEM (GST*STAGE_BYTES)      // 110592 B

template<bool RELU, bool RES, bool HALF_OUT>
__global__ __launch_bounds__(256, 2) void mma_gemm(
    const __half* __restrict__ A, const __half* __restrict__ Bt,
    const float* __restrict__ bias, const float* __restrict__ res,
    void* __restrict__ Cv, int M, int N, int K)
{
    extern __shared__ char smc[];
    const uint32_t sm_b = smem_u32(smc);

    const int tid  = threadIdx.x;
    const int lane = tid & 31, wid = tid >> 5;
    const int wm = wid >> 2, wn = wid & 3;        // 2 x 4 warp grid
    const int gid = lane >> 2, tg = lane & 3;
    const int bx = blockIdx.x, by = blockIdx.y;

    const __half* Ab = A  + (size_t)by * 128 * K;
    const __half* Bb = Bt + (size_t)bx * 128 * K;
    const int nchunks = K >> 6;                   // K/64

    // ldmatrix per-lane offsets (bytes) within a stage's A / B tile
    const int la7 = lane & 7;
    uint32_t offA[4], offB[4];
    {
        const int arow = la7 + ((lane >> 3) & 1) * 8;
        const int acol = (lane >> 4) * 8;
        #pragma unroll
        for (int mt = 0; mt < 4; mt++)
            offA[mt] = (uint32_t)(((wm*64 + mt*16 + arow)*LDH + acol) * 2);
        const int bcol = ((lane >> 3) & 1) * 8;
        #pragma unroll
        for (int nt = 0; nt < 4; nt++)
            offB[nt] = (uint32_t)(((wn*32 + nt*8 + la7)*LDH + bcol) * 2);
    }

    // Stage loader: 2 tiles x 128 rows x 64 halves (8x16B per row)
    auto load_stage = [&](int st, int kt) {
        const uint32_t a_dst = sm_b + (uint32_t)st*STAGE_BYTES;
        const uint32_t b_dst = a_dst + TILE_H*2;
        const __half* as = Ab + (size_t)kt*64;
        const __half* bs = Bb + (size_t)kt*64;
        #pragma unroll
        for (int it = 0; it < 4; it++) {
            const int idx = it*256 + tid;
            const int r = idx >> 3, c8 = idx & 7;
            const uint32_t off = (uint32_t)(r*144 + c8*16);
            CP_ASYNC16(a_dst + off, as + (size_t)r*K + c8*8);
            CP_ASYNC16(b_dst + off, bs + (size_t)r*K + c8*8);
        }
        CP_COMMIT();
    };

    float acc[4][4][4];
    #pragma unroll
    for (int i = 0; i < 4; i++)
        #pragma unroll
        for (int j = 0; j < 4; j++)
            #pragma unroll
            for (int k = 0; k < 4; k++) acc[i][j][k] = 0.f;

    cudaGridDependencySynchronize();

    load_stage(0, 0);
    if (nchunks > 1) load_stage(1, 1);

    for (int i = 0; i < nchunks; i++) {
        const int st = i % GST;
        if (i + 1 < nchunks) { CP_WAIT(1); } else { CP_WAIT(0); }
        __syncthreads();

        if (i + (GST-1) < nchunks)
            load_stage((i + GST - 1) % GST, i + GST - 1);

        const uint32_t aBase = sm_b + (uint32_t)st*STAGE_BYTES;
        const uint32_t bBase = aBase + TILE_H*2;

        #pragma unroll
        for (int kk = 0; kk < 4; kk++) {
            uint32_t a[4][4], b[4][2];
            #pragma unroll
            for (int mt = 0; mt < 4; mt++)
                LDSM_X4(a[mt][0], a[mt][1], a[mt][2], a[mt][3],
                        aBase + offA[mt] + kk*32);
            #pragma unroll
            for (int nt = 0; nt < 4; nt++)
                LDSM_X2(b[nt][0], b[nt][1], bBase + offB[nt] + kk*32);
            #pragma unroll
            for (int mt = 0; mt < 4; mt++)
                #pragma unroll
                for (int nt = 0; nt < 4; nt++)
                    MMA_F16(acc[mt][nt], a[mt], b[nt][0], b[nt][1]);
        }
        // no trailing barrier: next iteration's top sync protects stage reuse
    }

    // Epilogue
    #pragma unroll
    for (int mt = 0; mt < 4; mt++) {
        #pragma unroll
        for (int nt = 0; nt < 4; nt++) {
            const int r0 = by*128 + wm*64 + mt*16 + gid;
            const int c  = bx*128 + wn*32 + nt*8 + tg*2;
            const float2 b2 = *(const float2*)(bias + c);
            #pragma unroll
            for (int half_i = 0; half_i < 2; half_i++) {
                const int r = r0 + half_i*8;
                float ox = acc[mt][nt][half_i*2+0] + b2.x;
                float oy = acc[mt][nt][half_i*2+1] + b2.y;
                if (RELU) { ox = fmaxf(ox, 0.f); oy = fmaxf(oy, 0.f); }
                if (RES) {
                    const float2 r2 = *(const float2*)(res + (size_t)r*N + c);
                    ox += r2.x; oy += r2.y;
                }
                if (HALF_OUT) {
                    *(uint32_t*)((__half*)Cv + (size_t)r*N + c) = pack_h2(ox, oy);
                } else {
                    float2 o; o.x = ox; o.y = oy;
                    *(float2*)((float*)Cv + (size_t)r*N + c) = o;
                }
            }
        }
    }
}

// ---------------------------------------------------------------------------
// fp16 tensor-core causal flash attention, d_k=64, fused QKV input.
// CTA: 256 threads (8 warps), 128 q rows (16/warp), 64-key KV tiles,
// 3-stage cp.async ring, one barrier per KV tile, warp-uniform skip of the
// oacc rescale when the running max didn't change.
// ---------------------------------------------------------------------------
#define ALDH 72
#define ATILE_B (64*ALDH*2)               // 9216 B per 64x64 half tile
#define ATT_SMEM (6*ATILE_B)              // 3 stages x (K+V) = 55296 B
#define FA_C1 0.1803368801111204f          // log2(e)/8

__global__ __launch_bounds__(256) void fa_kernel(
    const __half* __restrict__ QKV, __half* __restrict__ O)
{
    extern __shared__ char fsc[];
    const int tid  = threadIdx.x;
    const int lane = tid & 31, w = tid >> 5;      // 8 warps
    const int gid  = lane >> 2, tg = lane & 3;
    const int qt   = (int)gridDim.x - 1 - (int)blockIdx.x;   // big tiles first
    const int bh   = blockIdx.y;
    const int b    = bh >> 4, h = bh & 15;
    const int qbase = qt * 128;
    const int n_kt  = 2*qt + 2;                   // 64-key tiles to process

    __half* Ks[3] = { (__half*)fsc,                 (__half*)(fsc + 2*ATILE_B),
                      (__half*)(fsc + 4*ATILE_B) };
    __half* Vs[3] = { (__half*)(fsc + ATILE_B),     (__half*)(fsc + 3*ATILE_B),
                      (__half*)(fsc + 5*ATILE_B) };

    // 64-row tile loader (256 threads, 2 chunks each)
    auto load_tile = [&](__half* dst, const __half* src) {
        const uint32_t d0 = smem_u32(dst);
        #pragma unroll
        for (int i = 0; i < 2; i++) {
            const int idx = i*256 + tid;
            const int r = idx >> 3, c8 = idx & 7;
            CP_ASYNC16(d0 + (uint32_t)(r*144 + c8*16), src + (size_t)r*QKVS + c8*8);
        }
    };

    const __half* Kg = QKV + (size_t)(b*SS)*QKVS + DM + h*DK;
    const __half* Vg = QKV + (size_t)(b*SS)*QKVS + 2*DM + h*DK;
    auto load_kv = [&](int st, int kt) {
        load_tile(Ks[st], Kg + (size_t)(kt*64)*QKVS);
        load_tile(Vs[st], Vg + (size_t)(kt*64)*QKVS);
        CP_COMMIT();
    };

    // ldmatrix per-lane offsets
    const int la7 = lane & 7;
    const uint32_t offQ = (uint32_t)(((w*16 + la7 + ((lane>>3)&1)*8)*ALDH
                                     + (lane>>4)*8) * 2);
    uint32_t offK[8];
    #pragma unroll
    for (int nt = 0; nt < 8; nt++)
        offK[nt] = (uint32_t)(((nt*8 + la7)*ALDH + ((lane>>3)&1)*8) * 2);

    cudaGridDependencySynchronize();

    // --- Stage 128-row Q tile through smem (uses Ks[0]+Vs[0] region) ---
    {
        const uint32_t d0 = smem_u32(fsc);
        const __half* qsrc = QKV + (size_t)(b*SS + qbase)*QKVS + h*DK;
        #pragma unroll
        for (int i = 0; i < 4; i++) {
            const int idx = i*256 + tid;
            const int r = idx >> 3, c8 = idx & 7;
            CP_ASYNC16(d0 + (uint32_t)(r*144 + c8*16), qsrc + (size_t)r*QKVS + c8*8);
        }
        CP_COMMIT();
        CP_WAIT(0);
    }
    __syncthreads();

    uint32_t qf[4][4];
    {
        const uint32_t qsB = smem_u32(fsc);
        #pragma unroll
        for (int kk = 0; kk < 4; kk++)
            LDSM_X4(qf[kk][0], qf[kk][1], qf[kk][2], qf[kk][3],
                    qsB + offQ + kk*32);
    }
    __syncthreads();

    load_kv(0, 0);
    if (n_kt > 1) load_kv(1, 1);

    float oacc[8][4];
    #pragma unroll
    for (int d = 0; d < 8; d++) {
        oacc[d][0] = 0.f; oacc[d][1] = 0.f; oacc[d][2] = 0.f; oacc[d][3] = 0.f;
    }
    float m0r = -INFINITY, m1r = -INFINITY, l0 = 0.f, l1 = 0.f;

    for (int kt = 0; kt < n_kt; kt++) {
        const int st = kt % 3;
        if (kt + 1 < n_kt) { CP_WAIT(1); } else { CP_WAIT(0); }
        __syncthreads();

        if (kt + 2 < n_kt) load_kv((kt + 2) % 3, kt + 2);

        const uint32_t ks_b = smem_u32(Ks[st]);
        const uint32_t vs_b = smem_u32(Vs[st]);

        // ---- S = Q K^T (unscaled) ----
        float sacc[8][4];
        #pragma unroll
        for (int nt = 0; nt < 8; nt++) {
            sacc[nt][0] = 0.f; sacc[nt][1] = 0.f; sacc[nt][2] = 0.f; sacc[nt][3] = 0.f;
        }
        #pragma unroll
        for (int kk = 0; kk < 4; kk++) {
            #pragma unroll
            for (int nt = 0; nt < 8; nt++) {
                uint32_t b0, b1;
                LDSM_X2(b0, b1, ks_b + offK[nt] + kk*32);
                MMA_F16(sacc[nt], qf[kk], b0, b1);
            }
        }

        // ---- causal mask (last two tiles only) ----
        if (kt >= n_kt - 2) {
            const int koff = kt*64 - qbase;       // 0 or 64
            const int q0 = w*16 + gid;
            #pragma unroll
            for (int nt = 0; nt < 8; nt++) {
                const int s0 = koff + nt*8 + 2*tg;
                if (s0     > q0)     sacc[nt][0] = -1e30f;
                if (s0 + 1 > q0)     sacc[nt][1] = -1e30f;
                if (s0     > q0 + 8) sacc[nt][2] = -1e30f;
                if (s0 + 1 > q0 + 8) sacc[nt][3] = -1e30f;
            }
        }

        // ---- online softmax in exp2 domain ----
        float t0 = -1e30f, t1 = -1e30f;
        #pragma unroll
        for (int nt = 0; nt < 8; nt++) {
            t0 = fmaxf(t0, fmaxf(sacc[nt][0], sacc[nt][1]));
            t1 = fmaxf(t1, fmaxf(sacc[nt][2], sacc[nt][3]));
        }
        t0 = fmaxf(t0, __shfl_xor_sync(0xffffffffu, t0, 1));
        t0 = fmaxf(t0, __shfl_xor_sync(0xffffffffu, t0, 2));
        t1 = fmaxf(t1, __shfl_xor_sync(0xffffffffu, t1, 1));
        t1 = fmaxf(t1, __shfl_xor_sync(0xffffffffu, t1, 2));

        const float mn0 = fmaxf(m0r, t0), mn1 = fmaxf(m1r, t1);
        const bool chg = (mn0 > m0r) || (mn1 > m1r);
        if (__any_sync(0xffffffffu, chg)) {
            const float cr0 = ex2((m0r - mn0) * FA_C1);
            const float cr1 = ex2((m1r - mn1) * FA_C1);
            l0 *= cr0; l1 *= cr1;
            #pragma unroll
            for (int d = 0; d < 8; d++) {
                oacc[d][0] *= cr0; oacc[d][1] *= cr0;
                oacc[d][2] *= cr1; oacc[d][3] *= cr1;
            }
        }
        m0r = mn0; m1r = mn1;

        const float mc0 = mn0 * FA_C1, mc1 = mn1 * FA_C1;
        float s0 = 0.f, s1 = 0.f;
        #pragma unroll
        for (int nt = 0; nt < 8; nt++) {
            const float p0 = ex2(fmaf(sacc[nt][0], FA_C1, -mc0));
            const float p1 = ex2(fmaf(sacc[nt][1], FA_C1, -mc0));
            const float p2 = ex2(fmaf(sacc[nt][2], FA_C1, -mc1));
            const float p3 = ex2(fmaf(sacc[nt][3], FA_C1, -mc1));
            s0 += p0 + p1; s1 += p2 + p3;
            sacc[nt][0] = p0; sacc[nt][1] = p1; sacc[nt][2] = p2; sacc[nt][3] = p3;
        }
        s0 += __shfl_xor_sync(0xffffffffu, s0, 1);
        s0 += __shfl_xor_sync(0xffffffffu, s0, 2);
        s1 += __shfl_xor_sync(0xffffffffu, s1, 1);
        s1 += __shfl_xor_sync(0xffffffffu, s1, 2);
        l0 += s0; l1 += s1;

        // ---- O += P V ----
        const int lm = lane >> 3, lr = lane & 7;
        #pragma unroll
        for (int j = 0; j < 4; j++) {
            uint32_t a[4];
            a[0] = pack_h2(sacc[2*j  ][0], sacc[2*j  ][1]);
            a[1] = pack_h2(sacc[2*j  ][2], sacc[2*j  ][3]);
            a[2] = pack_h2(sacc[2*j+1][0], sacc[2*j+1][1]);
            a[3] = pack_h2(sacc[2*j+1][2], sacc[2*j+1][3]);
            #pragma unroll
            for (int dtp = 0; dtp < 4; dtp++) {
                const int s_a = j*16 + ((lm & 1) << 3) + lr;
                const int d_a = dtp*16 + ((lm >> 1) << 3);
                const uint32_t addr = vs_b + (uint32_t)(s_a*ALDH + d_a)*2;
                uint32_t b0, b1, b2, b3;
                LDSM_X4_TRANS(b0, b1, b2, b3, addr);
                MMA_F16(oacc[dtp*2],   a, b0, b1);
                MMA_F16(oacc[dtp*2+1], a, b2, b3);
            }
        }
        // no trailing barrier: next iteration's top sync protects stage reuse
    }

    // ---- normalize + write (fp16; feeds Wo GEMM) ----
    const float inv0 = 1.0f / l0, inv1 = 1.0f / l1;
    const int r0 = b*SS + qbase + w*16 + gid;
    __half* o0 = O + (size_t)r0*DM + h*DK;
    __half* o1 = o0 + (size_t)8*DM;
    #pragma unroll
    for (int dt = 0; dt < 8; dt++) {
        const int c = dt*8 + 2*tg;
        *(uint32_t*)(o0 + c) = pack_h2(oacc[dt][0]*inv0, oacc[dt][1]*inv0);
        *(uint32_t*)(o1 + c) = pack_h2(oacc[dt][2]*inv1, oacc[dt][3]*inv1);
    }
}

// ---------------------------------------------------------------------------
// PDL launch helper: ProgrammaticStreamSerialization on dependent launches
// ---------------------------------------------------------------------------
template<typename F, typename... Args>
static inline void pdl_launch(F* f, dim3 g, dim3 b, size_t smem, Args... args) {
    cudaLaunchConfig_t cfg = {};
    cfg.gridDim = g; cfg.blockDim = b; cfg.dynamicSmemBytes = smem;
    cfg.stream = 0;
    cudaLaunchAttribute at[1];
    at[0].id = cudaLaunchAttributeProgrammaticStreamSerialization;
    at[0].val.programmaticStreamSerializationAllowed = 1;
    cfg.attrs = at; cfg.numAttrs = 1;
    cudaLaunchKernelEx(&cfg, f, args...);
}

// ---------------------------------------------------------------------------
// Launch
// ---------------------------------------------------------------------------
extern "C" void kernel_launch(void* const* d_in, const int* in_sizes, int n_in,
                              void* d_out, int out_size)
{
    const float* x   = (const float*)d_in[0];
    const float* Wq  = (const float*)d_in[1];
    const float* bq  = (const float*)d_in[2];
    const float* Wk  = (const float*)d_in[3];
    const float* bk  = (const float*)d_in[4];
    const float* Wv  = (const float*)d_in[5];
    const float* bv  = (const float*)d_in[6];
    const float* Wo  = (const float*)d_in[7];
    const float* bo  = (const float*)d_in[8];
    const float* W1  = (const float*)d_in[9];
    const float* b1  = (const float*)d_in[10];
    const float* W2  = (const float*)d_in[11];
    const float* b2  = (const float*)d_in[12];
    const float* g1  = (const float*)d_in[13];
    const float* be1 = (const float*)d_in[14];
    const float* g2  = (const float*)d_in[15];
    const float* be2 = (const float*)d_in[16];
    float* out = (float*)d_out;

    __half *p_h, *p_qkv, *p_o, *p_ff;
    __half *p_wqkvt, *p_wot, *p_w1t, *p_w2t;
    float  *p_x1, *p_bqkv;
    cudaGetSymbolAddress((void**)&p_h,     g_h);
    cudaGetSymbolAddress((void**)&p_qkv,   g_qkv);
    cudaGetSymbolAddress((void**)&p_o,     g_o);
    cudaGetSymbolAddress((void**)&p_x1,    g_x1);
    cudaGetSymbolAddress((void**)&p_ff,    g_ff);
    cudaGetSymbolAddress((void**)&p_wqkvt, g_wqkvt);
    cudaGetSymbolAddress((void**)&p_wot,   g_wot);
    cudaGetSymbolAddress((void**)&p_w1t,   g_w1t);
    cudaGetSymbolAddress((void**)&p_w2t,   g_w2t);
    cudaGetSymbolAddress((void**)&p_bqkv,  g_bqkv);

    static bool attr_set = false;
    if (!attr_set) {
        cudaFuncSetAttribute(mma_gemm<false,false,true>,
                             cudaFuncAttributeMaxDynamicSharedMemorySize, GEMM_SMEM);
        cudaFuncSetAttribute(mma_gemm<false,true,false>,
                             cudaFuncAttributeMaxDynamicSharedMemorySize, GEMM_SMEM);
        cudaFuncSetAttribute(mma_gemm<true,false,true>,
                             cudaFuncAttributeMaxDynamicSharedMemorySize, GEMM_SMEM);
        cudaFuncSetAttribute(fa_kernel,
                             cudaFuncAttributeMaxDynamicSharedMemorySize, ATT_SMEM);
        attr_set = true;
    }

    // 0. single prep launch: all transposes + bias concat
    prep_kernel<<<dim3(4096, 1, 6), 256>>>(
        Wq, Wk, Wv, Wo, W1, W2,
        p_wqkvt, p_wot, p_w1t, p_w2t, bq, bk, bv, p_bqkv);

    const dim3 gQKV(QKVS/128, MROWS/128);  // (24, 64)
    const dim3 gD  (DM/128,   MROWS/128);  // (8, 64)
    const dim3 gF  (DFF/128,  MROWS/128);  // (32, 64)
    const dim3 blk(256);

    // 1. ln1(x) -> h (fp16)
    pdl_launch(&ln_kernel, dim3(MROWS/8), blk, 0, x, g1, be1, p_h);
    // 2. fused QKV projection (fp16 tensor pipe, N=3072)
    pdl_launch(&mma_gemm<false,false,true>, gQKV, blk, (size_t)GEMM_SMEM,
               (const __half*)p_h, (const __half*)p_wqkvt, (const float*)p_bqkv,
               (const float*)nullptr, (void*)p_qkv, MROWS, QKVS, DM);
    // 3. causal attention (fp16 flash attention, 128-row q tiles)
    pdl_launch(&fa_kernel, dim3(SS/128, BB*HH), blk, (size_t)ATT_SMEM,
               (const __half*)p_qkv, p_o);
    // 4. output projection + residual(x) -> x1 (fp32)
    pdl_launch(&mma_gemm<false,true,false>, gD, blk, (size_t)GEMM_SMEM,
               (const __half*)p_o, (const __half*)p_wot, bo,
               x, (void*)p_x1, MROWS, DM, DM);
    // 5. ln2(x1) -> h (fp16)
    pdl_launch(&ln_kernel, dim3(MROWS/8), blk, 0,
               (const float*)p_x1, g2, be2, p_h);
    // 6. FFN up + ReLU (fp16 out)
    pdl_launch(&mma_gemm<true,false,true>, gF, blk, (size_t)GEMM_SMEM,
               (const __half*)p_h, (const __half*)p_w1t, b1,
               (const float*)nullptr, (void*)p_ff, MROWS, DFF, DM);
    // 7. FFN down + residual(x1) -> out (fp32)
    pdl_launch(&mma_gemm<false,true,false>, gD, blk, (size_t)GEMM_SMEM,
               (const __half*)p_ff, (const __half*)p_w2t, b2,
               (const float*)p_x1, (void*)out, MROWS, DM, DFF);
}

// round 13
// speedup vs baseline: 1.2050x; 1.0547x over previous
#include <cuda_runtime.h>
#include <cuda_fp16.h>
#include <math.h>
#include <stdint.h>

// Problem dimensions (fixed by the reference)
#define BB    4
#define SS    2048
#define DM    1024
#define HH    16
#define DK    64
#define DFF   4096
#define MROWS (BB*SS)          // 8192
#define QKVS  3072             // fused QKV row stride
#define LN_EPS 1e-5f

// ---------------------------------------------------------------------------
// Scratch (device globals; no allocations allowed)
// ---------------------------------------------------------------------------
__device__ __half g_h   [MROWS*DM];     // ln1 / ln2 output (fp16)
__device__ __half g_qkv [MROWS*QKVS];   // fused Q|K|V (fp16)
__device__ __half g_o   [MROWS*DM];     // attention output (fp16)
__device__ float  g_x1  [MROWS*DM];     // residual after attention (fp32)
__device__ __half g_ff  [MROWS*DFF];    // FFN hidden (fp16)
__device__ __half g_wqkvt[QKVS*DM];     // fused transposed weights [3072,1024]
__device__ __half g_wot [DM*DM];
__device__ __half g_w1t [DFF*DM];       // [4096,1024]
__device__ __half g_w2t [DM*DFF];       // [1024,4096]
__device__ float  g_bqkv[QKVS];         // fused bias

// ---------------------------------------------------------------------------
// Helpers
// ---------------------------------------------------------------------------
__device__ __forceinline__ uint32_t smem_u32(const void* p) {
    uint32_t a;
    asm("{ .reg .u64 t; cvta.to.shared.u64 t, %1; cvt.u32.u64 %0, t; }"
        : "=r"(a) : "l"(p));
    return a;
}

__device__ __forceinline__ uint32_t pack_h2(float lo, float hi) {
    __half2 h = __floats2half2_rn(lo, hi);
    return *reinterpret_cast<uint32_t*>(&h);
}

__device__ __forceinline__ float ex2(float x) {        // 2^x, MUFU.EX2
    float y;
    asm("ex2.approx.f32 %0, %1;" : "=f"(y) : "f"(x));
    return y;
}

#define CP_ASYNC16(dst, src) \
    asm volatile("cp.async.cg.shared.global [%0], [%1], 16;" :: "r"(dst), "l"(src))
#define CP_COMMIT()  asm volatile("cp.async.commit_group;" ::: "memory")
#define CP_WAIT(n)   asm volatile("cp.async.wait_group %0;" :: "n"(n) : "memory")

// m16n8k16 fp16 mma, fp32 accumulate
#define MMA_F16(d, a, b0, b1) \
    asm volatile("mma.sync.aligned.m16n8k16.row.col.f32.f16.f16.f32 " \
        "{%0,%1,%2,%3}, {%4,%5,%6,%7}, {%8,%9}, {%0,%1,%2,%3};" \
        : "+f"(d[0]), "+f"(d[1]), "+f"(d[2]), "+f"(d[3]) \
        : "r"(a[0]), "r"(a[1]), "r"(a[2]), "r"(a[3]), "r"(b0), "r"(b1))

#define LDSM_X4(r0, r1, r2, r3, addr) \
    asm volatile("ldmatrix.sync.aligned.m8n8.x4.shared.b16 {%0,%1,%2,%3}, [%4];" \
        : "=r"(r0), "=r"(r1), "=r"(r2), "=r"(r3) : "r"(addr))

#define LDSM_X4_TRANS(r0, r1, r2, r3, addr) \
    asm volatile("ldmatrix.sync.aligned.m8n8.x4.trans.shared.b16 {%0,%1,%2,%3}, [%4];" \
        : "=r"(r0), "=r"(r1), "=r"(r2), "=r"(r3) : "r"(addr))

// ---------------------------------------------------------------------------
// LayerNorm -> fp16, warp-per-row (8 rows per 256-thread block, no barriers)
// ---------------------------------------------------------------------------
__global__ __launch_bounds__(256) void ln_kernel(
    const float* __restrict__ X, const float* __restrict__ gamma,
    const float* __restrict__ beta, __half* __restrict__ out)
{
    const int t = threadIdx.x, lane = t & 31, w = t >> 5;
    const int row = blockIdx.x*8 + w;

    cudaGridDependencySynchronize();

    const float4* Xr = (const float4*)(X + (size_t)row*DM);
    float4 v[8];
    float s = 0.f, ss = 0.f;
    #pragma unroll
    for (int i = 0; i < 8; i++) {
        v[i] = Xr[lane + i*32];
        s  += v[i].x + v[i].y + v[i].z + v[i].w;
        ss += v[i].x*v[i].x + v[i].y*v[i].y + v[i].z*v[i].z + v[i].w*v[i].w;
    }
    #pragma unroll
    for (int o = 16; o > 0; o >>= 1) {
        s  += __shfl_xor_sync(0xffffffffu, s,  o);
        ss += __shfl_xor_sync(0xffffffffu, ss, o);
    }
    const float mu   = s * (1.0f / DM);
    const float var  = ss * (1.0f / DM) - mu*mu;
    const float rstd = rsqrtf(var + LN_EPS);

    const float4* G  = (const float4*)gamma;
    const float4* Bt = (const float4*)beta;
    uint2* Or = (uint2*)(out + (size_t)row*DM);
    #pragma unroll
    for (int i = 0; i < 8; i++) {
        const float4 g4 = G[lane + i*32];
        const float4 b4 = Bt[lane + i*32];
        uint2 st;
        st.x = pack_h2((v[i].x - mu)*rstd*g4.x + b4.x,
                       (v[i].y - mu)*rstd*g4.y + b4.y);
        st.y = pack_h2((v[i].z - mu)*rstd*g4.z + b4.z,
                       (v[i].w - mu)*rstd*g4.w + b4.w);
        Or[lane + i*32] = st;
    }
}

// ---------------------------------------------------------------------------
// Single prep kernel: z=0..5 -> transpose+round of Wq/Wk/Wv/Wo/W1/W2,
// bias concat folded into z=0 blocks 1024..1035. Grid (4096,1,6), block 256.
// ---------------------------------------------------------------------------
__global__ __launch_bounds__(256) void prep_kernel(
    const float* __restrict__ Wq, const float* __restrict__ Wk,
    const float* __restrict__ Wv, const float* __restrict__ Wo,
    const float* __restrict__ W1, const float* __restrict__ W2,
    __half* __restrict__ Tqkv, __half* __restrict__ To,
    __half* __restrict__ T1, __half* __restrict__ T2,
    const float* __restrict__ bq, const float* __restrict__ bk,
    const float* __restrict__ bv, float* __restrict__ bqkv)
{
    const int z = blockIdx.z;
    const float* W; __half* T; int K, N;
    switch (z) {
        case 0:  W = Wq; T = Tqkv;           K = DM;  N = DM;  break;
        case 1:  W = Wk; T = Tqkv + DM*DM;   K = DM;  N = DM;  break;
        case 2:  W = Wv; T = Tqkv + 2*DM*DM; K = DM;  N = DM;  break;
        case 3:  W = Wo; T = To;             K = DM;  N = DM;  break;
        case 4:  W = W1; T = T1;             K = DM;  N = DFF; break;
        default: W = W2; T = T2;             K = DFF; N = DM;  break;
    }
    // bias concat on z=0 blocks 1024..1035
    if (z == 0 && blockIdx.x >= 1024) {
        if (blockIdx.x < 1036) {
            const int i = (blockIdx.x - 1024)*256 + threadIdx.x;
            if (i < DM)        bqkv[i] = bq[i];
            else if (i < 2*DM) bqkv[i] = bk[i - DM];
            else               bqkv[i] = bv[i - 2*DM];
        }
        return;
    }
    const int nblk = N >> 5;
    const int bx = blockIdx.x % nblk, byk = blockIdx.x / nblk;
    if (byk >= (K >> 5)) return;

    __shared__ float tile[32][33];
    const int tx = threadIdx.x & 31, ty = threadIdx.x >> 5;
    const int n0 = bx*32, k0 = byk*32;
    #pragma unroll
    for (int i = ty; i < 32; i += 8)
        tile[i][tx] = W[(size_t)(k0 + i)*N + n0 + tx];
    __syncthreads();
    #pragma unroll
    for (int i = ty; i < 32; i += 8)
        T[(size_t)(n0 + i)*K + k0 + tx] = __float2half_rn(tile[tx][i]);
}

// ---------------------------------------------------------------------------
// fp16 mma.sync GEMM: C[M,N] = A[M,K] @ Bt[N,K]^T + bias (+relu)(+res)
// 128x128 CTA tile, BK=64, 3-stage cp.async, 256 threads (8 warps, 2x4),
// warp tile 64x32, ldmatrix x4 fragments (A and B), 2 CTAs/SM.
// ---------------------------------------------------------------------------
#define GST    3
#define LDH    72
#define TILE_H (128*LDH)                 // halves per tile (9216)
#define STAGE_BYTES (2*TILE_H*2)         // A + B = 36864 B
#define GEMM_SMEM (GST*STAGE_BYTES)      // 110592 B

template<bool RELU, bool RES, bool HALF_OUT>
__global__ __launch_bounds__(256, 2) void mma_gemm(
    const __half* __restrict__ A, const __half* __restrict__ Bt,
    const float* __restrict__ bias, const float* __restrict__ res,
    void* __restrict__ Cv, int M, int N, int K)
{
    extern __shared__ char smc[];
    const uint32_t sm_b = smem_u32(smc);

    const int tid  = threadIdx.x;
    const int lane = tid & 31, wid = tid >> 5;
    const int wm = wid >> 2, wn = wid & 3;        // 2 x 4 warp grid
    const int gid = lane >> 2, tg = lane & 3;
    const int bx = blockIdx.x, by = blockIdx.y;

    const __half* Ab = A  + (size_t)by * 128 * K;
    const __half* Bb = Bt + (size_t)bx * 128 * K;
    const int nchunks = K >> 6;                   // K/64

    // ldmatrix per-lane offsets (bytes) within a stage's A / B tile
    const int la7    = lane & 7;
    const int colsel = ((lane >> 3) & 1) << 3;    // 0/8 (k half)
    const int rowsel = (lane >> 4) << 3;          // 0/8 (row group)
    uint32_t offA[4], offB4[2];
    {
        const int arow = la7 + ((lane >> 3) & 1) * 8;
        const int acol = (lane >> 4) * 8;
        #pragma unroll
        for (int mt = 0; mt < 4; mt++)
            offA[mt] = (uint32_t)(((wm*64 + mt*16 + arow)*LDH + acol) * 2);
        #pragma unroll
        for (int g = 0; g < 2; g++)
            offB4[g] = (uint32_t)(((wn*32 + g*16 + la7 + rowsel)*LDH + colsel) * 2);
    }

    // Stage loader: 2 tiles x 128 rows x 64 halves (8x16B per row)
    auto load_stage = [&](int st, int kt) {
        const uint32_t a_dst = sm_b + (uint32_t)st*STAGE_BYTES;
        const uint32_t b_dst = a_dst + TILE_H*2;
        const __half* as = Ab + (size_t)kt*64;
        const __half* bs = Bb + (size_t)kt*64;
        #pragma unroll
        for (int it = 0; it < 4; it++) {
            const int idx = it*256 + tid;
            const int r = idx >> 3, c8 = idx & 7;
            const uint32_t off = (uint32_t)(r*144 + c8*16);
            CP_ASYNC16(a_dst + off, as + (size_t)r*K + c8*8);
            CP_ASYNC16(b_dst + off, bs + (size_t)r*K + c8*8);
        }
        CP_COMMIT();
    };

    float acc[4][4][4];
    #pragma unroll
    for (int i = 0; i < 4; i++)
        #pragma unroll
        for (int j = 0; j < 4; j++)
            #pragma unroll
            for (int k = 0; k < 4; k++) acc[i][j][k] = 0.f;

    cudaGridDependencySynchronize();

    load_stage(0, 0);
    if (nchunks > 1) load_stage(1, 1);

    for (int i = 0; i < nchunks; i++) {
        const int st = i % GST;
        if (i + 1 < nchunks) { CP_WAIT(1); } else { CP_WAIT(0); }
        __syncthreads();

        if (i + (GST-1) < nchunks)
            load_stage((i + GST - 1) % GST, i + GST - 1);

        const uint32_t aBase = sm_b + (uint32_t)st*STAGE_BYTES;
        const uint32_t bBase = aBase + TILE_H*2;

        #pragma unroll
        for (int kk = 0; kk < 4; kk++) {
            uint32_t a[4][4], b[2][4];
            #pragma unroll
            for (int mt = 0; mt < 4; mt++)
                LDSM_X4(a[mt][0], a[mt][1], a[mt][2], a[mt][3],
                        aBase + offA[mt] + kk*32);
            #pragma unroll
            for (int g = 0; g < 2; g++)
                LDSM_X4(b[g][0], b[g][1], b[g][2], b[g][3],
                        bBase + offB4[g] + kk*32);
            #pragma unroll
            for (int mt = 0; mt < 4; mt++) {
                #pragma unroll
                for (int g = 0; g < 2; g++) {
                    MMA_F16(acc[mt][2*g],   a[mt], b[g][0], b[g][1]);
                    MMA_F16(acc[mt][2*g+1], a[mt], b[g][2], b[g][3]);
                }
            }
        }
        // no trailing barrier: next iteration's top sync protects stage reuse
    }

    // Epilogue
    #pragma unroll
    for (int mt = 0; mt < 4; mt++) {
        #pragma unroll
        for (int nt = 0; nt < 4; nt++) {
            const int r0 = by*128 + wm*64 + mt*16 + gid;
            const int c  = bx*128 + wn*32 + nt*8 + tg*2;
            const float2 b2 = *(const float2*)(bias + c);
            #pragma unroll
            for (int half_i = 0; half_i < 2; half_i++) {
                const int r = r0 + half_i*8;
                float ox = acc[mt][nt][half_i*2+0] + b2.x;
                float oy = acc[mt][nt][half_i*2+1] + b2.y;
                if (RELU) { ox = fmaxf(ox, 0.f); oy = fmaxf(oy, 0.f); }
                if (RES) {
                    const float2 r2 = *(const float2*)(res + (size_t)r*N + c);
                    ox += r2.x; oy += r2.y;
                }
                if (HALF_OUT) {
                    *(uint32_t*)((__half*)Cv + (size_t)r*N + c) = pack_h2(ox, oy);
                } else {
                    float2 o; o.x = ox; o.y = oy;
                    *(float2*)((float*)Cv + (size_t)r*N + c) = o;
                }
            }
        }
    }
}

// ---------------------------------------------------------------------------
// fp16 tensor-core causal flash attention, d_k=64, fused QKV input.
// CTA: 256 threads (8 warps), 128 q rows (16/warp), 64-key KV tiles,
// 4-stage cp.async ring (&3 indexing), one barrier per KV tile, K frags via
// ldmatrix.x4, warp-level skip of fully masked tiles.
// ---------------------------------------------------------------------------
#define ALDH 72
#define ATILE_B (64*ALDH*2)               // 9216 B per 64x64 half tile
#define ATT_SMEM (8*ATILE_B)              // 4 stages x (K+V) = 73728 B
#define FA_C1 0.1803368801111204f          // log2(e)/8

__global__ __launch_bounds__(256, 2) void fa_kernel(
    const __half* __restrict__ QKV, __half* __restrict__ O)
{
    extern __shared__ char fsc[];
    const int tid  = threadIdx.x;
    const int lane = tid & 31, w = tid >> 5;      // 8 warps
    const int gid  = lane >> 2, tg = lane & 3;
    const int qt   = (int)gridDim.x - 1 - (int)blockIdx.x;   // big tiles first
    const int bh   = blockIdx.y;
    const int b    = bh >> 4, h = bh & 15;
    const int qbase = qt * 128;
    const int n_kt  = 2*qt + 2;                   // 64-key tiles to process

    const uint32_t fs_b = smem_u32(fsc);

    // 64-row tile loader (256 threads, 2 chunks each)
    auto load_tile = [&](uint32_t d0, const __half* src) {
        #pragma unroll
        for (int i = 0; i < 2; i++) {
            const int idx = i*256 + tid;
            const int r = idx >> 3, c8 = idx & 7;
            CP_ASYNC16(d0 + (uint32_t)(r*144 + c8*16), src + (size_t)r*QKVS + c8*8);
        }
    };

    const __half* Kg = QKV + (size_t)(b*SS)*QKVS + DM + h*DK;
    const __half* Vg = QKV + (size_t)(b*SS)*QKVS + 2*DM + h*DK;
    auto load_kv = [&](int st, int kt) {
        load_tile(fs_b + (uint32_t)st*(2*ATILE_B),           Kg + (size_t)(kt*64)*QKVS);
        load_tile(fs_b + (uint32_t)st*(2*ATILE_B) + ATILE_B, Vg + (size_t)(kt*64)*QKVS);
        CP_COMMIT();
    };

    // ldmatrix per-lane offsets
    const int la7    = lane & 7;
    const int colsel = ((lane >> 3) & 1) << 3;    // 0/8 (k half)
    const int rowsel = (lane >> 4) << 3;          // 0/8 (row pair group)
    const uint32_t offQ = (uint32_t)(((w*16 + la7 + ((lane>>3)&1)*8)*ALDH
                                     + (lane>>4)*8) * 2);
    uint32_t offK4[4];
    #pragma unroll
    for (int g = 0; g < 4; g++)
        offK4[g] = (uint32_t)(((g*16 + la7 + rowsel)*ALDH + colsel) * 2);

    cudaGridDependencySynchronize();

    // --- Stage 128-row Q tile through smem (stage 0+1 region) ---
    {
        const __half* qsrc = QKV + (size_t)(b*SS + qbase)*QKVS + h*DK;
        #pragma unroll
        for (int i = 0; i < 4; i++) {
            const int idx = i*256 + tid;
            const int r = idx >> 3, c8 = idx & 7;
            CP_ASYNC16(fs_b + (uint32_t)(r*144 + c8*16), qsrc + (size_t)r*QKVS + c8*8);
        }
        CP_COMMIT();
        CP_WAIT(0);
    }
    __syncthreads();

    uint32_t qf[4][4];
    #pragma unroll
    for (int kk = 0; kk < 4; kk++)
        LDSM_X4(qf[kk][0], qf[kk][1], qf[kk][2], qf[kk][3],
                fs_b + offQ + kk*32);
    __syncthreads();

    load_kv(0, 0);
    if (n_kt > 1) load_kv(1, 1);

    float oacc[8][4];
    #pragma unroll
    for (int d = 0; d < 8; d++) {
        oacc[d][0] = 0.f; oacc[d][1] = 0.f; oacc[d][2] = 0.f; oacc[d][3] = 0.f;
    }
    float m0r = -INFINITY, m1r = -INFINITY, l0 = 0.f, l1 = 0.f;

    for (int kt = 0; kt < n_kt; kt++) {
        const int st = kt & 3;
        if (kt + 1 < n_kt) { CP_WAIT(1); } else { CP_WAIT(0); }
        __syncthreads();

        if (kt + 2 < n_kt) load_kv((kt + 2) & 3, kt + 2);

        // warps 0-3 (q rows qbase..qbase+63): last tile is fully masked
        if (kt == n_kt - 1 && w < 4) continue;

        const uint32_t ks_b = fs_b + (uint32_t)st*(2*ATILE_B);
        const uint32_t vs_b = ks_b + ATILE_B;

        // ---- S = Q K^T (unscaled), K frags via ldmatrix.x4 ----
        float sacc[8][4];
        #pragma unroll
        for (int nt = 0; nt < 8; nt++) {
            sacc[nt][0] = 0.f; sacc[nt][1] = 0.f; sacc[nt][2] = 0.f; sacc[nt][3] = 0.f;
        }
        #pragma unroll
        for (int kk = 0; kk < 4; kk++) {
            #pragma unroll
            for (int g = 0; g < 4; g++) {
                uint32_t b0, b1, b2, b3;
                LDSM_X4(b0, b1, b2, b3, ks_b + offK4[g] + kk*32);
                MMA_F16(sacc[2*g],   qf[kk], b0, b1);
                MMA_F16(sacc[2*g+1], qf[kk], b2, b3);
            }
        }

        // ---- causal mask (only where it can bite) ----
        if (kt == n_kt - 1 || (kt == n_kt - 2 && w < 4)) {
            const int koff = kt*64 - qbase;       // 0 or 64
            const int q0 = w*16 + gid;
            #pragma unroll
            for (int nt = 0; nt < 8; nt++) {
                const int s0 = koff + nt*8 + 2*tg;
                if (s0     > q0)     sacc[nt][0] = -1e30f;
                if (s0 + 1 > q0)     sacc[nt][1] = -1e30f;
                if (s0     > q0 + 8) sacc[nt][2] = -1e30f;
                if (s0 + 1 > q0 + 8) sacc[nt][3] = -1e30f;
            }
        }

        // ---- online softmax in exp2 domain ----
        float t0 = -1e30f, t1 = -1e30f;
        #pragma unroll
        for (int nt = 0; nt < 8; nt++) {
            t0 = fmaxf(t0, fmaxf(sacc[nt][0], sacc[nt][1]));
            t1 = fmaxf(t1, fmaxf(sacc[nt][2], sacc[nt][3]));
        }
        t0 = fmaxf(t0, __shfl_xor_sync(0xffffffffu, t0, 1));
        t0 = fmaxf(t0, __shfl_xor_sync(0xffffffffu, t0, 2));
        t1 = fmaxf(t1, __shfl_xor_sync(0xffffffffu, t1, 1));
        t1 = fmaxf(t1, __shfl_xor_sync(0xffffffffu, t1, 2));

        const float mn0 = fmaxf(m0r, t0), mn1 = fmaxf(m1r, t1);
        const bool chg = (mn0 > m0r) || (mn1 > m1r);
        if (__any_sync(0xffffffffu, chg)) {
            const float cr0 = ex2((m0r - mn0) * FA_C1);
            const float cr1 = ex2((m1r - mn1) * FA_C1);
            l0 *= cr0; l1 *= cr1;
            #pragma unroll
            for (int d = 0; d < 8; d++) {
                oacc[d][0] *= cr0; oacc[d][1] *= cr0;
                oacc[d][2] *= cr1; oacc[d][3] *= cr1;
            }
        }
        m0r = mn0; m1r = mn1;

        const float mc0 = mn0 * FA_C1, mc1 = mn1 * FA_C1;
        float s0 = 0.f, s1 = 0.f;
        #pragma unroll
        for (int nt = 0; nt < 8; nt++) {
            const float p0 = ex2(fmaf(sacc[nt][0], FA_C1, -mc0));
            const float p1 = ex2(fmaf(sacc[nt][1], FA_C1, -mc0));
            const float p2 = ex2(fmaf(sacc[nt][2], FA_C1, -mc1));
            const float p3 = ex2(fmaf(sacc[nt][3], FA_C1, -mc1));
            s0 += p0 + p1; s1 += p2 + p3;
            sacc[nt][0] = p0; sacc[nt][1] = p1; sacc[nt][2] = p2; sacc[nt][3] = p3;
        }
        s0 += __shfl_xor_sync(0xffffffffu, s0, 1);
        s0 += __shfl_xor_sync(0xffffffffu, s0, 2);
        s1 += __shfl_xor_sync(0xffffffffu, s1, 1);
        s1 += __shfl_xor_sync(0xffffffffu, s1, 2);
        l0 += s0; l1 += s1;

        // ---- O += P V ----
        const int lm = lane >> 3, lr = lane & 7;
        #pragma unroll
        for (int j = 0; j < 4; j++) {
            uint32_t a[4];
            a[0] = pack_h2(sacc[2*j  ][0], sacc[2*j  ][1]);
            a[1] = pack_h2(sacc[2*j  ][2], sacc[2*j  ][3]);
            a[2] = pack_h2(sacc[2*j+1][0], sacc[2*j+1][1]);
            a[3] = pack_h2(sacc[2*j+1][2], sacc[2*j+1][3]);
            #pragma unroll
            for (int dtp = 0; dtp < 4; dtp++) {
                const int s_a = j*16 + ((lm & 1) << 3) + lr;
                const int d_a = dtp*16 + ((lm >> 1) << 3);
                const uint32_t addr = vs_b + (uint32_t)(s_a*ALDH + d_a)*2;
                uint32_t b0, b1, b2, b3;
                LDSM_X4_TRANS(b0, b1, b2, b3, addr);
                MMA_F16(oacc[dtp*2],   a, b0, b1);
                MMA_F16(oacc[dtp*2+1], a, b2, b3);
            }
        }
        // no trailing barrier: next iteration's top sync protects stage reuse
    }

    // ---- normalize + write (fp16; feeds Wo GEMM) ----
    const float inv0 = 1.0f / l0, inv1 = 1.0f / l1;
    const int r0 = b*SS + qbase + w*16 + gid;
    __half* o0 = O + (size_t)r0*DM + h*DK;
    __half* o1 = o0 + (size_t)8*DM;
    #pragma unroll
    for (int dt = 0; dt < 8; dt++) {
        const int c = dt*8 + 2*tg;
        *(uint32_t*)(o0 + c) = pack_h2(oacc[dt][0]*inv0, oacc[dt][1]*inv0);
        *(uint32_t*)(o1 + c) = pack_h2(oacc[dt][2]*inv1, oacc[dt][3]*inv1);
    }
}

// ---------------------------------------------------------------------------
// PDL launch helper: ProgrammaticStreamSerialization on dependent launches
// ---------------------------------------------------------------------------
template<typename F, typename... Args>
static inline void pdl_launch(F* f, dim3 g, dim3 b, size_t smem, Args... args) {
    cudaLaunchConfig_t cfg = {};
    cfg.gridDim = g; cfg.blockDim = b; cfg.dynamicSmemBytes = smem;
    cfg.stream = 0;
    cudaLaunchAttribute at[1];
    at[0].id = cudaLaunchAttributeProgrammaticStreamSerialization;
    at[0].val.programmaticStreamSerializationAllowed = 1;
    cfg.attrs = at; cfg.numAttrs = 1;
    cudaLaunchKernelEx(&cfg, f, args...);
}

// ---------------------------------------------------------------------------
// Launch
// ---------------------------------------------------------------------------
extern "C" void kernel_launch(void* const* d_in, const int* in_sizes, int n_in,
                              void* d_out, int out_size)
{
    const float* x   = (const float*)d_in[0];
    const float* Wq  = (const float*)d_in[1];
    const float* bq  = (const float*)d_in[2];
    const float* Wk  = (const float*)d_in[3];
    const float* bk  = (const float*)d_in[4];
    const float* Wv  = (const float*)d_in[5];
    const float* bv  = (const float*)d_in[6];
    const float* Wo  = (const float*)d_in[7];
    const float* bo  = (const float*)d_in[8];
    const float* W1  = (const float*)d_in[9];
    const float* b1  = (const float*)d_in[10];
    const float* W2  = (const float*)d_in[11];
    const float* b2  = (const float*)d_in[12];
    const float* g1  = (const float*)d_in[13];
    const float* be1 = (const float*)d_in[14];
    const float* g2  = (const float*)d_in[15];
    const float* be2 = (const float*)d_in[16];
    float* out = (float*)d_out;

    __half *p_h, *p_qkv, *p_o, *p_ff;
    __half *p_wqkvt, *p_wot, *p_w1t, *p_w2t;
    float  *p_x1, *p_bqkv;
    cudaGetSymbolAddress((void**)&p_h,     g_h);
    cudaGetSymbolAddress((void**)&p_qkv,   g_qkv);
    cudaGetSymbolAddress((void**)&p_o,     g_o);
    cudaGetSymbolAddress((void**)&p_x1,    g_x1);
    cudaGetSymbolAddress((void**)&p_ff,    g_ff);
    cudaGetSymbolAddress((void**)&p_wqkvt, g_wqkvt);
    cudaGetSymbolAddress((void**)&p_wot,   g_wot);
    cudaGetSymbolAddress((void**)&p_w1t,   g_w1t);
    cudaGetSymbolAddress((void**)&p_w2t,   g_w2t);
    cudaGetSymbolAddress((void**)&p_bqkv,  g_bqkv);

    static bool attr_set = false;
    if (!attr_set) {
        cudaFuncSetAttribute(mma_gemm<false,false,true>,
                             cudaFuncAttributeMaxDynamicSharedMemorySize, GEMM_SMEM);
        cudaFuncSetAttribute(mma_gemm<false,true,false>,
                             cudaFuncAttributeMaxDynamicSharedMemorySize, GEMM_SMEM);
        cudaFuncSetAttribute(mma_gemm<true,false,true>,
                             cudaFuncAttributeMaxDynamicSharedMemorySize, GEMM_SMEM);
        cudaFuncSetAttribute(fa_kernel,
                             cudaFuncAttributeMaxDynamicSharedMemorySize, ATT_SMEM);
        attr_set = true;
    }

    // 0. single prep launch: all transposes + bias concat
    prep_kernel<<<dim3(4096, 1, 6), 256>>>(
        Wq, Wk, Wv, Wo, W1, W2,
        p_wqkvt, p_wot, p_w1t, p_w2t, bq, bk, bv, p_bqkv);

    const dim3 gQKV(QKVS/128, MROWS/128);  // (24, 64)
    const dim3 gD  (DM/128,   MROWS/128);  // (8, 64)
    const dim3 gF  (DFF/128,  MROWS/128);  // (32, 64)
    const dim3 blk(256);

    // 1. ln1(x) -> h (fp16)
    pdl_launch(&ln_kernel, dim3(MROWS/8), blk, 0, x, g1, be1, p_h);
    // 2. fused QKV projection (fp16 tensor pipe, N=3072)
    pdl_launch(&mma_gemm<false,false,true>, gQKV, blk, (size_t)GEMM_SMEM,
               (const __half*)p_h, (const __half*)p_wqkvt, (const float*)p_bqkv,
               (const float*)nullptr, (void*)p_qkv, MROWS, QKVS, DM);
    // 3. causal attention (fp16 flash attention, 128-row q tiles)
    pdl_launch(&fa_kernel, dim3(SS/128, BB*HH), blk, (size_t)ATT_SMEM,
               (const __half*)p_qkv, p_o);
    // 4. output projection + residual(x) -> x1 (fp32)
    pdl_launch(&mma_gemm<false,true,false>, gD, blk, (size_t)GEMM_SMEM,
               (const __half*)p_o, (const __half*)p_wot, bo,
               x, (void*)p_x1, MROWS, DM, DM);
    // 5. ln2(x1) -> h (fp16)
    pdl_launch(&ln_kernel, dim3(MROWS/8), blk, 0,
               (const float*)p_x1, g2, be2, p_h);
    // 6. FFN up + ReLU (fp16 out)
    pdl_launch(&mma_gemm<true,false,true>, gF, blk, (size_t)GEMM_SMEM,
               (const __half*)p_h, (const __half*)p_w1t, b1,
               (const float*)nullptr, (void*)p_ff, MROWS, DFF, DM);
    // 7. FFN down + residual(x1) -> out (fp32)
    pdl_launch(&mma_gemm<false,true,false>, gD, blk, (size_t)GEMM_SMEM,
               (const __half*)p_ff, (const __half*)p_w2t, b2,
               (const float*)p_x1, (void*)out, MROWS, DM, DFF);
}